// round 7
// baseline (speedup 1.0000x reference)
#include <cuda_runtime.h>
#include <cuda_bf16.h>
#include <math.h>

#define BQ   128
#define SQ   32
#define INQ  512
#define HQ   1024
#define OUTQ 512
#define NQ   16384
#define WQ   128
#define CQ   899
#define CP   960
#define K1   1664
#define KR   1152
#define KSL  384
#define G4   4096
#define HRP  576
#define HOW  1088
#define NCHUNK 256
#define MQ   4096

// ---------------- device globals ----------------
__device__ float sc_mem[NQ * WQ];
__device__ float sc_Wcat[G4 * K1];
__device__ __nv_bfloat16 sc_WrH[G4 * KR];
__device__ __nv_bfloat16 sc_WrL[G4 * KR];
__device__ float sc_bg[G4];
__device__ float sc_WoutP[CP * HQ];
__device__ float sc_HW[HRP * CP];
__device__ float sc_Hb[HRP];
__device__ float sc_HOW[HOW * HQ];
__device__ float sc_HOb[HOW];
__device__ float sc_xg[(long long)MQ * G4];
__device__ float sc_g3[3 * BQ * G4];
__device__ float sc_h[BQ * HQ];
__device__ float sc_c[BQ * HQ];
__device__ __nv_bfloat16 sc_AH[BQ * KR];
__device__ __nv_bfloat16 sc_AL[BQ * KR];
__device__ float sc_rw[BQ * NQ];
__device__ float sc_ww[BQ * NQ];
__device__ float sc_heads[BQ * HRP];
__device__ __nv_bfloat16 sc_keysH[2 * BQ * WQ];
__device__ __nv_bfloat16 sc_keysL[2 * BQ * WQ];
__device__ __nv_bfloat16 sc_memnH[NQ * WQ];
__device__ __nv_bfloat16 sc_memnL[NQ * WQ];
__device__ float sc_beta[2 * BQ];
__device__ float sc_gamma[2 * BQ];
__device__ float sc_er[BQ * WQ];
__device__ float sc_ad[BQ * WQ];
__device__ float sc_sim[2 * BQ * NQ];
__device__ float sc_rvpart[NCHUNK * BQ * WQ];

// ---------------- helpers ----------------
__device__ __forceinline__ float sigmoidf_(float x) { return 1.0f / (1.0f + expf(-x)); }
__device__ __forceinline__ float softplusf_(float x) { return x > 20.0f ? x : log1pf(expf(x)); }

__device__ __forceinline__ void bsplit(float v, __nv_bfloat16* h, __nv_bfloat16* l) {
    __nv_bfloat16 hi = __float2bfloat16(v);
    *h = hi;
    *l = __float2bfloat16(v - __bfloat162float(hi));
}

__device__ __forceinline__ void st_bf2(__nv_bfloat16* p, __nv_bfloat16 a, __nv_bfloat16 b) {
    __nv_bfloat162 t;
    t.x = a;
    t.y = b;
    *(__nv_bfloat162*)p = t;
}

__device__ __forceinline__ unsigned sptr(const void* p) {
    return (unsigned)__cvta_generic_to_shared(p);
}

__device__ __forceinline__ void ldm_x4(unsigned* r, unsigned a) {
    asm volatile("ldmatrix.sync.aligned.m8n8.x4.shared.b16 {%0,%1,%2,%3}, [%4];"
        : "=r"(r[0]), "=r"(r[1]), "=r"(r[2]), "=r"(r[3]) : "r"(a));
}

__device__ __forceinline__ void ldm_x2(unsigned* r, unsigned a) {
    asm volatile("ldmatrix.sync.aligned.m8n8.x2.shared.b16 {%0,%1}, [%2];"
        : "=r"(r[0]), "=r"(r[1]) : "r"(a));
}

__device__ __forceinline__ void mma_bf16(float* d, const unsigned* a, const unsigned* b) {
    asm volatile("mma.sync.aligned.m16n8k16.row.col.f32.bf16.bf16.f32 "
        "{%0,%1,%2,%3}, {%4,%5,%6,%7}, {%8,%9}, {%0,%1,%2,%3};"
        : "+f"(d[0]), "+f"(d[1]), "+f"(d[2]), "+f"(d[3])
        : "r"(a[0]), "r"(a[1]), "r"(a[2]), "r"(a[3]), "r"(b[0]), "r"(b[1]));
}

__device__ __forceinline__ float blockSum128(float v, float* sh) {
    #pragma unroll
    for (int o = 16; o; o >>= 1) v += __shfl_xor_sync(0xffffffffu, v, o);
    if ((threadIdx.x & 31) == 0) sh[threadIdx.x >> 5] = v;
    __syncthreads();
    float r = sh[0] + sh[1] + sh[2] + sh[3];
    __syncthreads();
    return r;
}

// ---------------- prologue kernels ----------------
__global__ void k_build_wcat(const float* __restrict__ Wih, const float* __restrict__ Whh) {
    long long idx = (long long)blockIdx.x * blockDim.x + threadIdx.x;
    if (idx >= (long long)G4 * K1) return;
    int r = (int)(idx / K1);
    int k = (int)(idx % K1);
    int src = (r & 3) * HQ + (r >> 2);
    sc_Wcat[idx] = (k < INQ + WQ) ? Wih[src * (INQ + WQ) + k] : Whh[src * HQ + (k - INQ - WQ)];
}

__global__ void k_split_wcat() {
    long long idx = (long long)blockIdx.x * blockDim.x + threadIdx.x;
    if (idx >= (long long)G4 * KR) return;
    int r = (int)(idx / KR);
    int k = (int)(idx % KR);
    __nv_bfloat16 h, l;
    bsplit(sc_Wcat[(long long)r * K1 + INQ + k], &h, &l);
    sc_WrH[idx] = h;
    sc_WrL[idx] = l;
}

__global__ void k_build_bg(const float* __restrict__ bih, const float* __restrict__ bhh) {
    int r = blockIdx.x * blockDim.x + threadIdx.x;
    if (r >= G4) return;
    int src = (r & 3) * HQ + (r >> 2);
    sc_bg[r] = bih[src] + bhh[src];
}

__global__ void k_build_woutp(const float* __restrict__ Wout) {
    long long idx = (long long)blockIdx.x * blockDim.x + threadIdx.x;
    if (idx >= (long long)CP * HQ) return;
    int r = (int)(idx / HQ);
    int k = (int)(idx % HQ);
    sc_WoutP[idx] = (r < CQ) ? Wout[(long long)r * HQ + k] : 0.0f;
}

__global__ void k_build_hw(const float* rkW, const float* rbW, const float* rgW,
                           const float* wkW, const float* wbW, const float* wgW,
                           const float* erW, const float* adW,
                           const float* rkb, const float* rbb, const float* rgb,
                           const float* wkb, const float* wbb, const float* wgb,
                           const float* erb, const float* adb) {
    int idx = blockIdx.x * blockDim.x + threadIdx.x;
    if (idx >= HRP * CP) return;
    int r = idx / CP;
    int k = idx % CP;
    float wv = 0.0f;
    float bv = 0.0f;
    if (k < CQ && r < 516) {
        if (r < 128)       { wv = rkW[r * CQ + k];         bv = rkb[r]; }
        else if (r == 128) { wv = rbW[k];                  bv = rbb[0]; }
        else if (r == 129) { wv = rgW[k];                  bv = rgb[0]; }
        else if (r < 258)  { wv = wkW[(r - 130) * CQ + k]; bv = wkb[r - 130]; }
        else if (r == 258) { wv = wbW[k];                  bv = wbb[0]; }
        else if (r == 259) { wv = wgW[k];                  bv = wgb[0]; }
        else if (r < 388)  { wv = erW[(r - 260) * CQ + k]; bv = erb[r - 260]; }
        else               { wv = adW[(r - 388) * CQ + k]; bv = adb[r - 388]; }
    }
    sc_HW[idx] = wv;
    if (k == 0) sc_Hb[r] = bv;
}

__global__ void k_init(const float* __restrict__ memory) {
    long long i = (long long)blockIdx.x * blockDim.x + threadIdx.x;
    if (i < (long long)NQ * WQ) {
        sc_mem[i] = memory[i];
        sc_rw[i] = 1.0f / (float)NQ;
    }
    if (i < BQ * HQ) {
        sc_h[i] = 0.0f;
        sc_c[i] = 0.0f;
    }
    if (i < BQ * KR / 2) {
        ((unsigned*)sc_AH)[i] = 0u;
        ((unsigned*)sc_AL)[i] = 0u;
    }
}

__global__ void k_memn0() {
    int row = blockIdx.x * (blockDim.x >> 5) + (threadIdx.x >> 5);
    int lane = threadIdx.x & 31;
    if (row >= NQ) return;
    const float* r = sc_mem + (long long)row * WQ;
    float v[4];
    float s = 0.f;
    #pragma unroll
    for (int i = 0; i < 4; i++) { v[i] = r[lane + 32 * i]; s += v[i] * v[i]; }
    #pragma unroll
    for (int o = 16; o; o >>= 1) s += __shfl_xor_sync(0xffffffffu, s, o);
    float inv = 1.0f / fmaxf(sqrtf(s), 1e-12f);
    #pragma unroll
    for (int i = 0; i < 4; i++) {
        __nv_bfloat16 h, l;
        bsplit(v[i] * inv, &h, &l);
        sc_memnH[(long long)row * WQ + lane + 32 * i] = h;
        sc_memnL[(long long)row * WQ + lane + 32 * i] = l;
    }
}

__global__ __launch_bounds__(128) void k_biases(const float* __restrict__ bout,
                                                const float* __restrict__ pW,
                                                const float* __restrict__ pb) {
    __shared__ float sh[4];
    int r = blockIdx.x;
    int t = threadIdx.x;
    float s = 0.f;
    if (r < HRP) {
        for (int c = t; c < CQ; c += 128) s += sc_HW[r * CP + c] * bout[c];
        s = blockSum128(s, sh);
        if (t == 0) sc_HOb[r] = s + sc_Hb[r];
    } else {
        int o = r - HRP;
        for (int c = t; c < OUTQ; c += 128) s += pW[o * OUTQ + c] * bout[c];
        s = blockSum128(s, sh);
        if (t == 0) sc_HOb[r] = s + pb[o];
    }
}

// HOW rows 0..575 = HW @ WoutP ; rows 576..1087 = pW @ Wout[:512]
__global__ __launch_bounds__(256) void k_fold(const float* __restrict__ pW,
                                              const float* __restrict__ Wout) {
    __shared__ float As[32][36];
    __shared__ float Bs[32][36];
    int tid = threadIdx.x;
    int n0 = blockIdx.x * 32;
    int second = (blockIdx.y >= 18) ? 1 : 0;
    int m0 = second ? (blockIdx.y - 18) * 32 : blockIdx.y * 32;
    const float* A = second ? pW : sc_HW;
    const float* B = second ? Wout : sc_WoutP;
    int lda = second ? OUTQ : CP;
    int K = second ? OUTQ : CP;
    int dstRow = second ? HRP : 0;
    int rowL = tid >> 3;
    int k4 = (tid & 7) * 4;
    int tm = tid & 7;
    int tn = tid >> 3;
    float acc[4] = {};
    for (int k0 = 0; k0 < K; k0 += 32) {
        float4 a = *(const float4*)(A + (long long)(m0 + rowL) * lda + k0 + k4);
        float4 b = *(const float4*)(B + (long long)(k0 + rowL) * HQ + n0 + k4);
        As[rowL][k4 + 0] = a.x; As[rowL][k4 + 1] = a.y; As[rowL][k4 + 2] = a.z; As[rowL][k4 + 3] = a.w;
        Bs[rowL][k4 + 0] = b.x; Bs[rowL][k4 + 1] = b.y; Bs[rowL][k4 + 2] = b.z; Bs[rowL][k4 + 3] = b.w;
        __syncthreads();
        #pragma unroll
        for (int k = 0; k < 32; k++) {
            float bv = Bs[k][tn];
            #pragma unroll
            for (int i = 0; i < 4; i++) acc[i] = fmaf(As[tm * 4 + i][k], bv, acc[i]);
        }
        __syncthreads();
    }
    #pragma unroll
    for (int i = 0; i < 4; i++)
        sc_HOW[(long long)(dstRow + m0 + tm * 4 + i) * HQ + n0 + tn] = acc[i];
}

__global__ __launch_bounds__(256) void k_xg(const float* __restrict__ x) {
    __shared__ float As[16][68];
    __shared__ float Bs[16][68];
    int tid = threadIdx.x;
    int n0 = blockIdx.x * 64;
    int m0 = blockIdx.y * 64;
    int rowL = tid >> 2;
    int k4 = (tid & 3) * 4;
    int txm = tid & 15;
    int txn = tid >> 4;
    float acc[4][4] = {};
    int m = m0 + rowL;
    const float* arow = x + ((long long)(m & 127) * SQ + (m >> 7)) * INQ;
    const float* brow = sc_Wcat + (long long)(n0 + rowL) * K1;
    for (int k0 = 0; k0 < INQ; k0 += 16) {
        float4 a = *(const float4*)(arow + k0 + k4);
        float4 b = *(const float4*)(brow + k0 + k4);
        As[k4 + 0][rowL] = a.x; As[k4 + 1][rowL] = a.y; As[k4 + 2][rowL] = a.z; As[k4 + 3][rowL] = a.w;
        Bs[k4 + 0][rowL] = b.x; Bs[k4 + 1][rowL] = b.y; Bs[k4 + 2][rowL] = b.z; Bs[k4 + 3][rowL] = b.w;
        __syncthreads();
        #pragma unroll
        for (int k = 0; k < 16; k++) {
            float4 av = *(const float4*)&As[k][txm * 4];
            float4 bv = *(const float4*)&Bs[k][txn * 4];
            float aa[4] = {av.x, av.y, av.z, av.w};
            float bb[4] = {bv.x, bv.y, bv.z, bv.w};
            #pragma unroll
            for (int i = 0; i < 4; i++) {
                #pragma unroll
                for (int j = 0; j < 4; j++) acc[i][j] = fmaf(aa[i], bb[j], acc[i][j]);
            }
        }
        __syncthreads();
    }
    #pragma unroll
    for (int i = 0; i < 4; i++) {
        long long mi = m0 + txm * 4 + i;
        #pragma unroll
        for (int j = 0; j < 4; j++)
            sc_xg[mi * G4 + n0 + txn * 4 + j] = acc[i][j];
    }
}

// ---------------- per-step kernels ----------------
__global__ __launch_bounds__(256) void k_lstm_mma() {
    __shared__ __nv_bfloat16 AHs[64][24];
    __shared__ __nv_bfloat16 ALs[64][24];
    __shared__ __nv_bfloat16 BHs[128][24];
    __shared__ __nv_bfloat16 BLs[128][24];
    int tid = threadIdx.x;
    int n0 = blockIdx.x * 128;
    int m0 = blockIdx.y * 64;
    int ks = blockIdx.z;
    int w = tid >> 5;
    int lane = tid & 31;
    int mBase = (w >> 2) * 32;
    int nBase = (w & 3) * 32;
    float acc[2][4][4] = {};
    const unsigned* gAH = (const unsigned*)sc_AH;
    const unsigned* gAL = (const unsigned*)sc_AL;
    const unsigned* gBH = (const unsigned*)sc_WrH;
    const unsigned* gBL = (const unsigned*)sc_WrL;
    int kw0 = ks * (KSL / 2);
    for (int kc = 0; kc < KSL / 16; kc++) {
        for (int i = tid; i < 512; i += 256) {
            int r = i >> 3;
            int q = i & 7;
            ((unsigned*)AHs[r])[q] = gAH[(m0 + r) * (KR / 2) + kw0 + kc * 8 + q];
            ((unsigned*)ALs[r])[q] = gAL[(m0 + r) * (KR / 2) + kw0 + kc * 8 + q];
        }
        for (int i = tid; i < 1024; i += 256) {
            int r = i >> 3;
            int q = i & 7;
            ((unsigned*)BHs[r])[q] = gBH[(long long)(n0 + r) * (KR / 2) + kw0 + kc * 8 + q];
            ((unsigned*)BLs[r])[q] = gBL[(long long)(n0 + r) * (KR / 2) + kw0 + kc * 8 + q];
        }
        __syncthreads();
        unsigned ah[2][4];
        unsigned al[2][4];
        #pragma unroll
        for (int mt = 0; mt < 2; mt++) {
            int ar = mBase + mt * 16 + (lane & 15);
            int ac = (lane >> 4) * 8;
            ldm_x4(ah[mt], sptr(&AHs[ar][ac]));
            ldm_x4(al[mt], sptr(&ALs[ar][ac]));
        }
        #pragma unroll
        for (int j = 0; j < 4; j++) {
            int q = lane & 15;
            int br = nBase + j * 8 + (q & 7);
            int bc = (q >> 3) * 8;
            unsigned bh[2];
            unsigned bl[2];
            ldm_x2(bh, sptr(&BHs[br][bc]));
            ldm_x2(bl, sptr(&BLs[br][bc]));
            #pragma unroll
            for (int mt = 0; mt < 2; mt++) {
                mma_bf16(acc[mt][j], ah[mt], bh);
                mma_bf16(acc[mt][j], ah[mt], bl);
                mma_bf16(acc[mt][j], al[mt], bh);
            }
        }
        __syncthreads();
    }
    float* dst = sc_g3 + (long long)ks * BQ * G4;
    #pragma unroll
    for (int mt = 0; mt < 2; mt++) {
        int r = m0 + mBase + mt * 16 + (lane >> 2);
        #pragma unroll
        for (int j = 0; j < 4; j++) {
            int cc = n0 + nBase + j * 8 + (lane & 3) * 2;
            float2 v0 = make_float2(acc[mt][j][0], acc[mt][j][1]);
            float2 v1 = make_float2(acc[mt][j][2], acc[mt][j][3]);
            *(float2*)&dst[(long long)r * G4 + cc] = v0;
            *(float2*)&dst[(long long)(r + 8) * G4 + cc] = v1;
        }
    }
}

__global__ __launch_bounds__(256) void k_sim_mma() {
    __shared__ __nv_bfloat16 AHs[64][24];
    __shared__ __nv_bfloat16 ALs[64][24];
    __shared__ __nv_bfloat16 BHs[128][24];
    __shared__ __nv_bfloat16 BLs[128][24];
    int tid = threadIdx.x;
    int n0 = blockIdx.x * 128;
    int m0 = blockIdx.y * 64;
    int w = tid >> 5;
    int lane = tid & 31;
    int mBase = (w >> 2) * 32;
    int nBase = (w & 3) * 32;
    float acc[2][4][4] = {};
    const unsigned* gAH = (const unsigned*)sc_keysH;
    const unsigned* gAL = (const unsigned*)sc_keysL;
    const unsigned* gBH = (const unsigned*)sc_memnH;
    const unsigned* gBL = (const unsigned*)sc_memnL;
    for (int kc = 0; kc < WQ / 16; kc++) {
        for (int i = tid; i < 512; i += 256) {
            int r = i >> 3;
            int q = i & 7;
            ((unsigned*)AHs[r])[q] = gAH[(m0 + r) * (WQ / 2) + kc * 8 + q];
            ((unsigned*)ALs[r])[q] = gAL[(m0 + r) * (WQ / 2) + kc * 8 + q];
        }
        for (int i = tid; i < 1024; i += 256) {
            int r = i >> 3;
            int q = i & 7;
            ((unsigned*)BHs[r])[q] = gBH[(long long)(n0 + r) * (WQ / 2) + kc * 8 + q];
            ((unsigned*)BLs[r])[q] = gBL[(long long)(n0 + r) * (WQ / 2) + kc * 8 + q];
        }
        __syncthreads();
        unsigned ah[2][4];
        unsigned al[2][4];
        #pragma unroll
        for (int mt = 0; mt < 2; mt++) {
            int ar = mBase + mt * 16 + (lane & 15);
            int ac = (lane >> 4) * 8;
            ldm_x4(ah[mt], sptr(&AHs[ar][ac]));
            ldm_x4(al[mt], sptr(&ALs[ar][ac]));
        }
        #pragma unroll
        for (int j = 0; j < 4; j++) {
            int q = lane & 15;
            int br = nBase + j * 8 + (q & 7);
            int bc = (q >> 3) * 8;
            unsigned bh[2];
            unsigned bl[2];
            ldm_x2(bh, sptr(&BHs[br][bc]));
            ldm_x2(bl, sptr(&BLs[br][bc]));
            #pragma unroll
            for (int mt = 0; mt < 2; mt++) {
                mma_bf16(acc[mt][j], ah[mt], bh);
                mma_bf16(acc[mt][j], ah[mt], bl);
                mma_bf16(acc[mt][j], al[mt], bh);
            }
        }
        __syncthreads();
    }
    #pragma unroll
    for (int mt = 0; mt < 2; mt++) {
        int r = m0 + mBase + mt * 16 + (lane >> 2);
        #pragma unroll
        for (int j = 0; j < 4; j++) {
            int cc = n0 + nBase + j * 8 + (lane & 3) * 2;
            float2 v0 = make_float2(acc[mt][j][0], acc[mt][j][1]);
            float2 v1 = make_float2(acc[mt][j][2], acc[mt][j][3]);
            *(float2*)&sc_sim[(long long)r * NQ + cc] = v0;
            *(float2*)&sc_sim[(long long)(r + 8) * NQ + cc] = v1;
        }
    }
}

__global__ __launch_bounds__(256) void k_gates(int s) {
    int idx = blockIdx.x * blockDim.x + threadIdx.x;
    if (idx >= BQ * HQ) return;
    int b = idx >> 10;
    int u = idx & 1023;
    long long off = (long long)b * G4 + u * 4;
    float4 p0 = *(const float4*)&sc_g3[off];
    float4 p1 = *(const float4*)&sc_g3[(long long)BQ * G4 + off];
    float4 p2 = *(const float4*)&sc_g3[(long long)2 * BQ * G4 + off];
    float4 xg = *(const float4*)&sc_xg[((long long)s * BQ + b) * G4 + u * 4];
    float4 bg = *(const float4*)&sc_bg[u * 4];
    float i_ = p0.x + p1.x + p2.x + xg.x + bg.x;
    float f_ = p0.y + p1.y + p2.y + xg.y + bg.y;
    float g_ = p0.z + p1.z + p2.z + xg.z + bg.z;
    float o_ = p0.w + p1.w + p2.w + xg.w + bg.w;
    float c = sigmoidf_(f_) * sc_c[idx] + sigmoidf_(i_) * tanhf(g_);
    sc_c[idx] = c;
    float hv = sigmoidf_(o_) * tanhf(c);
    sc_h[idx] = hv;
    __nv_bfloat16 h;
    __nv_bfloat16 l;
    bsplit(hv, &h, &l);
    sc_AH[b * KR + WQ + u] = h;
    sc_AL[b * KR + WQ + u] = l;
}

__global__ __launch_bounds__(256) void k_headsout(float* __restrict__ out, int s) {
    __shared__ float As[32][33];
    __shared__ float Bs[32][33];
    int tid = threadIdx.x;
    int n0 = blockIdx.x * 32;
    int m0 = blockIdx.y * 32;
    int rowL = tid >> 3;
    int k4 = (tid & 7) * 4;
    int tm = tid & 7;
    int tn = tid >> 3;
    float acc[4] = {};
    for (int k0 = 0; k0 < HQ; k0 += 32) {
        float4 a = *(const float4*)(sc_h + (long long)(m0 + rowL) * HQ + k0 + k4);
        float4 b = *(const float4*)(sc_HOW + (long long)(n0 + rowL) * HQ + k0 + k4);
        As[rowL][k4 + 0] = a.x; As[rowL][k4 + 1] = a.y; As[rowL][k4 + 2] = a.z; As[rowL][k4 + 3] = a.w;
        Bs[rowL][k4 + 0] = b.x; Bs[rowL][k4 + 1] = b.y; Bs[rowL][k4 + 2] = b.z; Bs[rowL][k4 + 3] = b.w;
        __syncthreads();
        #pragma unroll
        for (int k = 0; k < 32; k++) {
            float bv = Bs[tn][k];
            #pragma unroll
            for (int i = 0; i < 4; i++) acc[i] = fmaf(As[tm * 4 + i][k], bv, acc[i]);
        }
        __syncthreads();
    }
    int n = n0 + tn;
    float bb = sc_HOb[n];
    #pragma unroll
    for (int i = 0; i < 4; i++) {
        int m = m0 + tm * 4 + i;
        float v = acc[i] + bb;
        if (n < HRP) sc_heads[m * HRP + n] = v;
        else out[((long long)m * SQ + s) * OUTQ + (n - HRP)] = v;
    }
}

__global__ __launch_bounds__(128) void k_headproc() {
    __shared__ float sh[4];
    int b = blockIdx.x;
    int w = threadIdx.x;
    const float* hd = sc_heads + b * HRP;
    float rk = hd[w];
    float wk = hd[130 + w];
    float nr2 = blockSum128(rk * rk, sh);
    float nw2 = blockSum128(wk * wk, sh);
    __nv_bfloat16 h;
    __nv_bfloat16 l;
    bsplit(rk / fmaxf(sqrtf(nr2), 1e-12f), &h, &l);
    sc_keysH[b * WQ + w] = h;
    sc_keysL[b * WQ + w] = l;
    bsplit(wk / fmaxf(sqrtf(nw2), 1e-12f), &h, &l);
    sc_keysH[(128 + b) * WQ + w] = h;
    sc_keysL[(128 + b) * WQ + w] = l;
    if (w == 0) {
        sc_beta[b] = softplusf_(hd[128]);
        sc_gamma[b] = 1.0f + softplusf_(hd[129]);
        sc_beta[128 + b] = softplusf_(hd[258]);
        sc_gamma[128 + b] = 1.0f + softplusf_(hd[259]);
    }
    sc_er[b * WQ + w] = sigmoidf_(hd[260 + w]);
    sc_ad[b * WQ + w] = tanhf(hd[388 + w]);
}

__global__ __launch_bounds__(512) void k_softmax512() {
    __shared__ float sh[16];
    __shared__ float bcv;
    int q = blockIdx.x;
    int tid = threadIdx.x;
    int lane = tid & 31;
    int wid = tid >> 5;
    float beta = sc_beta[q];
    float gamma = sc_gamma[q];
    const float* row = sc_sim + (long long)q * NQ;
    float v[32];
    float mx = -1e30f;
    #pragma unroll
    for (int i = 0; i < 32; i++) { v[i] = row[tid + i * 512]; mx = fmaxf(mx, v[i]); }
    #pragma unroll
    for (int o = 16; o; o >>= 1) mx = fmaxf(mx, __shfl_xor_sync(0xffffffffu, mx, o));
    if (lane == 0) sh[wid] = mx;
    __syncthreads();
    if (tid == 0) {
        float m = sh[0];
        #pragma unroll
        for (int i = 1; i < 16; i++) m = fmaxf(m, sh[i]);
        bcv = m;
    }
    __syncthreads();
    mx = bcv;
    float s = 0.f;
    #pragma unroll
    for (int i = 0; i < 32; i++) { v[i] = __expf(beta * (v[i] - mx)); s += v[i]; }
    __syncthreads();
    #pragma unroll
    for (int o = 16; o; o >>= 1) s += __shfl_xor_sync(0xffffffffu, s, o);
    if (lane == 0) sh[wid] = s;
    __syncthreads();
    if (tid == 0) {
        float t = 0.f;
        #pragma unroll
        for (int i = 0; i < 16; i++) t += sh[i];
        bcv = 1.0f / t;
    }
    __syncthreads();
    float inv = bcv;
    if (q < 128) {
        float* rw = sc_rw + (long long)q * NQ;
        #pragma unroll
        for (int i = 0; i < 32; i++) {
            int n = tid + i * 512;
            rw[n] = gamma * (v[i] * inv) + (1.0f - gamma) * rw[n];
        }
    } else {
        float* ww = sc_ww + (long long)(q - 128) * NQ;
        float u = (1.0f - gamma) * (1.0f / (float)NQ);
        #pragma unroll
        for (int i = 0; i < 32; i++) {
            ww[tid + i * 512] = gamma * (v[i] * inv) + u;
        }
    }
}

__global__ __launch_bounds__(256) void k_memupd_rv() {
    __shared__ __align__(16) float mns[64][132];
    __shared__ __align__(16) float ubuf[2656];
    __shared__ float rowsq[64][4];
    __shared__ float sInv[64];
    float (*sw)[68] = (float(*)[68])ubuf;
    float (*se)[132] = (float(*)[132])(ubuf + 8 * 68);
    float (*sa)[132] = (float(*)[132])(ubuf + 8 * 68 + 8 * 132);
    float (*srw)[132] = (float(*)[132])ubuf;
    int tid = threadIdx.x;
    int n0 = blockIdx.x * 64;
    int txn = tid & 15;
    int txw = tid >> 4;
    float ae[4][8] = {};
    float aa[4][8] = {};
    for (int b0 = 0; b0 < BQ; b0 += 8) {
        int kk = tid >> 5;
        int half = tid & 31;
        *(float2*)&sw[kk][half * 2] = *(const float2*)&sc_ww[(long long)(b0 + kk) * NQ + n0 + half * 2];
        *(float4*)&se[kk][half * 4] = *(const float4*)&sc_er[(b0 + kk) * WQ + half * 4];
        *(float4*)&sa[kk][half * 4] = *(const float4*)&sc_ad[(b0 + kk) * WQ + half * 4];
        __syncthreads();
        #pragma unroll
        for (int k = 0; k < 8; k++) {
            float4 w4 = *(const float4*)&sw[k][txn * 4];
            float4 e0 = *(const float4*)&se[k][txw * 8];
            float4 e1 = *(const float4*)&se[k][txw * 8 + 4];
            float4 a0 = *(const float4*)&sa[k][txw * 8];
            float4 a1 = *(const float4*)&sa[k][txw * 8 + 4];
            float wv[4] = {w4.x, w4.y, w4.z, w4.w};
            float ev[8] = {e0.x, e0.y, e0.z, e0.w, e1.x, e1.y, e1.z, e1.w};
            float av[8] = {a0.x, a0.y, a0.z, a0.w, a1.x, a1.y, a1.z, a1.w};
            #pragma unroll
            for (int i = 0; i < 4; i++) {
                #pragma unroll
                for (int j = 0; j < 8; j++) {
                    ae[i][j] = fmaf(wv[i], ev[j], ae[i][j]);
                    aa[i][j] = fmaf(wv[i], av[j], aa[i][j]);
                }
            }
        }
        __syncthreads();
    }
    #pragma unroll
    for (int i = 0; i < 4; i++) {
        int nl = txn * 4 + i;
        long long base = (long long)(n0 + nl) * WQ + txw * 8;
        float4 m0v = *(const float4*)&sc_mem[base];
        float4 m1v = *(const float4*)&sc_mem[base + 4];
        float r[8] = {m0v.x, m0v.y, m0v.z, m0v.w, m1v.x, m1v.y, m1v.z, m1v.w};
        #pragma unroll
        for (int j = 0; j < 8; j++) r[j] = r[j] * (1.0f - ae[i][j]) + aa[i][j];
        *(float4*)&sc_mem[base] = make_float4(r[0], r[1], r[2], r[3]);
        *(float4*)&sc_mem[base + 4] = make_float4(r[4], r[5], r[6], r[7]);
        *(float4*)&mns[nl][txw * 8] = make_float4(r[0], r[1], r[2], r[3]);
        *(float4*)&mns[nl][txw * 8 + 4] = make_float4(r[4], r[5], r[6], r[7]);
    }
    __syncthreads();
    {
        int r = tid >> 2;
        int qq = tid & 3;
        float s = 0.f;
        #pragma unroll
        for (int t = 0; t < 32; t += 4) {
            float4 v = *(const float4*)&mns[r][qq * 32 + t];
            s += v.x * v.x + v.y * v.y + v.z * v.z + v.w * v.w;
        }
        rowsq[r][qq] = s;
    }
    __syncthreads();
    if (tid < 64) {
        float s = rowsq[tid][0] + rowsq[tid][1] + rowsq[tid][2] + rowsq[tid][3];
        sInv[tid] = 1.0f / fmaxf(sqrtf(s), 1e-12f);
    }
    __syncthreads();
    for (int i = tid; i < 64 * 32; i += 256) {
        int r = i >> 5;
        int c = (i & 31) * 4;
        float inv = sInv[r];
        float4 v = *(const float4*)&mns[r][c];
        __nv_bfloat16 h0, l0, h1, l1, h2, l2, h3, l3;
        bsplit(v.x * inv, &h0, &l0);
        bsplit(v.y * inv, &h1, &l1);
        bsplit(v.z * inv, &h2, &l2);
        bsplit(v.w * inv, &h3, &l3);
        long long o = (long long)(n0 + r) * WQ + c;
        st_bf2(&sc_memnH[o], h0, h1);
        st_bf2(&sc_memnH[o + 2], h2, h3);
        st_bf2(&sc_memnL[o], l0, l1);
        st_bf2(&sc_memnL[o + 2], l2, l3);
    }
    int tb = tid & 15;
    int tw = tid >> 4;
    float racc[8][8] = {};
    for (int nc = 0; nc < 4; nc++) {
        __syncthreads();
        #pragma unroll
        for (int r = 0; r < 8; r++) {
            int b = tw + r * 16;
            srw[tb][b] = sc_rw[(long long)b * NQ + n0 + nc * 16 + tb];
        }
        __syncthreads();
        #pragma unroll
        for (int nn = 0; nn < 16; nn++) {
            float4 r0 = *(const float4*)&srw[nn][tb * 8];
            float4 r1 = *(const float4*)&srw[nn][tb * 8 + 4];
            int nl = nc * 16 + nn;
            float4 q0 = *(const float4*)&mns[nl][tw * 8];
            float4 q1 = *(const float4*)&mns[nl][tw * 8 + 4];
            float rb[8] = {r0.x, r0.y, r0.z, r0.w, r1.x, r1.y, r1.z, r1.w};
            float mw[8] = {q0.x, q0.y, q0.z, q0.w, q1.x, q1.y, q1.z, q1.w};
            #pragma unroll
            for (int i = 0; i < 8; i++) {
                #pragma unroll
                for (int j = 0; j < 8; j++) racc[i][j] = fmaf(rb[i], mw[j], racc[i][j]);
            }
        }
    }
    float* dst = sc_rvpart + (long long)blockIdx.x * BQ * WQ;
    #pragma unroll
    for (int i = 0; i < 8; i++) {
        int b = tb * 8 + i;
        *(float4*)&dst[b * WQ + tw * 8] = make_float4(racc[i][0], racc[i][1], racc[i][2], racc[i][3]);
        *(float4*)&dst[b * WQ + tw * 8 + 4] = make_float4(racc[i][4], racc[i][5], racc[i][6], racc[i][7]);
    }
}

__global__ __launch_bounds__(256) void k_rvreduce() {
    __shared__ float4 red[32][8];
    int tid = threadIdx.x;
    int outIdx = blockIdx.x * 32 + (tid >> 3);
    int sub = tid & 7;
    const float4* p = (const float4*)sc_rvpart;
    float4 s = make_float4(0.f, 0.f, 0.f, 0.f);
    #pragma unroll 4
    for (int i = 0; i < 32; i++) {
        float4 t = p[(long long)(sub + i * 8) * 4096 + outIdx];
        s.x += t.x; s.y += t.y; s.z += t.z; s.w += t.w;
    }
    red[tid >> 3][sub] = s;
    __syncthreads();
    if (sub == 0) {
        float4 a = make_float4(0.f, 0.f, 0.f, 0.f);
        #pragma unroll
        for (int i = 0; i < 8; i++) {
            float4 t = red[tid >> 3][i];
            a.x += t.x; a.y += t.y; a.z += t.z; a.w += t.w;
        }
        int b = outIdx >> 5;
        int c0 = (outIdx & 31) * 4;
        __nv_bfloat16 h0, l0, h1, l1, h2, l2, h3, l3;
        bsplit(a.x, &h0, &l0);
        bsplit(a.y, &h1, &l1);
        bsplit(a.z, &h2, &l2);
        bsplit(a.w, &h3, &l3);
        int o = b * KR + c0;
        st_bf2(&sc_AH[o], h0, h1);
        st_bf2(&sc_AH[o + 2], h2, h3);
        st_bf2(&sc_AL[o], l0, l1);
        st_bf2(&sc_AL[o + 2], l2, l3);
    }
}

// ---------------- host launcher ----------------
extern "C" void kernel_launch(void* const* d_in, const int* in_sizes, int n_in,
                              void* d_out, int out_size) {
    const float* x = (const float*)d_in[0];
    const float* memory = (const float*)d_in[1];
    const float* Wih = (const float*)d_in[2];
    const float* Whh = (const float*)d_in[3];
    const float* bih = (const float*)d_in[4];
    const float* bhh = (const float*)d_in[5];
    const float* Wout = (const float*)d_in[6];
    const float* bout = (const float*)d_in[7];
    const float* rkW = (const float*)d_in[8];
    const float* rkb = (const float*)d_in[9];
    const float* rbW = (const float*)d_in[10];
    const float* rbb = (const float*)d_in[11];
    const float* rgW = (const float*)d_in[12];
    const float* rgb = (const float*)d_in[13];
    const float* wkW = (const float*)d_in[14];
    const float* wkb = (const float*)d_in[15];
    const float* wbW = (const float*)d_in[16];
    const float* wbb = (const float*)d_in[17];
    const float* wgW = (const float*)d_in[18];
    const float* wgb = (const float*)d_in[19];
    const float* erW = (const float*)d_in[20];
    const float* erb = (const float*)d_in[21];
    const float* adW = (const float*)d_in[22];
    const float* adb = (const float*)d_in[23];
    const float* pW = (const float*)d_in[24];
    const float* pb = (const float*)d_in[25];
    float* out = (float*)d_out;

    k_build_wcat<<<(int)(((long long)G4 * K1 + 255) / 256), 256>>>(Wih, Whh);
    k_split_wcat<<<(int)(((long long)G4 * KR + 255) / 256), 256>>>();
    k_build_bg<<<(G4 + 255) / 256, 256>>>(bih, bhh);
    k_build_woutp<<<(int)(((long long)CP * HQ + 255) / 256), 256>>>(Wout);
    k_build_hw<<<(HRP * CP + 255) / 256, 256>>>(rkW, rbW, rgW, wkW, wbW, wgW, erW, adW,
                                                rkb, rbb, rgb, wkb, wbb, wgb, erb, adb);
    k_init<<<(int)(((long long)NQ * WQ + 511) / 512), 512>>>(memory);
    k_memn0<<<NQ / 8, 256>>>();
    k_xg<<<dim3(G4 / 64, MQ / 64), 256>>>(x);
    k_fold<<<dim3(HQ / 32, 34), 256>>>(pW, Wout);
    k_biases<<<HRP + OUTQ, 128>>>(bout, pW, pb);

    for (int s = 0; s < SQ; s++) {
        k_lstm_mma<<<dim3(G4 / 128, BQ / 64, 3), 256>>>();
        k_gates<<<(BQ * HQ + 255) / 256, 256>>>(s);
        k_headsout<<<dim3(HOW / 32, BQ / 32), 256>>>(out, s);
        k_headproc<<<BQ, 128>>>();
        k_sim_mma<<<dim3(NQ / 128, 4), 256>>>();
        k_softmax512<<<2 * BQ, 512>>>();
        k_memupd_rv<<<NQ / 64, 256>>>();
        k_rvreduce<<<128, 256>>>();
    }
}

// round 8
// speedup vs baseline: 1.3321x; 1.3321x over previous
#include <cuda_runtime.h>
#include <cuda_bf16.h>
#include <math.h>

#define BQ   128
#define SQ   32
#define INQ  512
#define HQ   1024
#define OUTQ 512
#define NQ   16384
#define WQ   128
#define CQ   899
#define CP   960
#define KR   1152
#define G4   4096
#define HRP  576
#define HOW  1088
#define NCHUNK 256
#define MQ   4096

// ---------------- device globals ----------------
__device__ float sc_mem[NQ * WQ];
__device__ float sc_WcatX[G4 * INQ];        // x-part weights (for xg precompute)
__device__ __nv_bfloat16 sc_WrH[G4 * KR];
__device__ __nv_bfloat16 sc_WrL[G4 * KR];
__device__ float sc_bg[G4];
__device__ float sc_WoutP[CP * HQ];
__device__ float sc_HW[HRP * CP];
__device__ float sc_HOW[HOW * HQ];
__device__ float sc_HOb[HOW];
__device__ float sc_xg[(long long)MQ * G4];
__device__ float sc_g3[3 * BQ * G4];
__device__ float sc_h[BQ * HQ];
__device__ float sc_c[BQ * HQ];
__device__ __nv_bfloat16 sc_AH[BQ * KR];
__device__ __nv_bfloat16 sc_AL[BQ * KR];
__device__ float sc_rw[BQ * NQ];
__device__ float sc_ww[BQ * NQ];
__device__ float sc_heads[BQ * HRP];
__device__ __nv_bfloat16 sc_keysH[2 * BQ * WQ];
__device__ __nv_bfloat16 sc_keysL[2 * BQ * WQ];
__device__ __nv_bfloat16 sc_memnH[NQ * WQ];
__device__ __nv_bfloat16 sc_memnL[NQ * WQ];
__device__ float sc_beta[2 * BQ];
__device__ float sc_gamma[2 * BQ];
__device__ float sc_er[BQ * WQ];
__device__ float sc_ad[BQ * WQ];
__device__ float sc_sim[2 * BQ * NQ];
__device__ float sc_rvpart[NCHUNK * BQ * WQ];

// ---------------- helpers ----------------
__device__ __forceinline__ float sigmoidf_(float x) { return 1.0f / (1.0f + expf(-x)); }
__device__ __forceinline__ float softplusf_(float x) { return x > 20.0f ? x : log1pf(expf(x)); }

__device__ __forceinline__ void bsplit(float v, __nv_bfloat16* h, __nv_bfloat16* l) {
    __nv_bfloat16 hi = __float2bfloat16(v);
    *h = hi;
    *l = __float2bfloat16(v - __bfloat162float(hi));
}

__device__ __forceinline__ void st_bf2(__nv_bfloat16* p, __nv_bfloat16 a, __nv_bfloat16 b) {
    __nv_bfloat162 t;
    t.x = a;
    t.y = b;
    *(__nv_bfloat162*)p = t;
}

__device__ __forceinline__ unsigned sptr(const void* p) {
    return (unsigned)__cvta_generic_to_shared(p);
}

__device__ __forceinline__ void ldm_x4(unsigned* r, unsigned a) {
    asm volatile("ldmatrix.sync.aligned.m8n8.x4.shared.b16 {%0,%1,%2,%3}, [%4];"
        : "=r"(r[0]), "=r"(r[1]), "=r"(r[2]), "=r"(r[3]) : "r"(a));
}

__device__ __forceinline__ void ldm_x2(unsigned* r, unsigned a) {
    asm volatile("ldmatrix.sync.aligned.m8n8.x2.shared.b16 {%0,%1}, [%2];"
        : "=r"(r[0]), "=r"(r[1]) : "r"(a));
}

__device__ __forceinline__ void mma_bf16(float* d, const unsigned* a, const unsigned* b) {
    asm volatile("mma.sync.aligned.m16n8k16.row.col.f32.bf16.bf16.f32 "
        "{%0,%1,%2,%3}, {%4,%5,%6,%7}, {%8,%9}, {%0,%1,%2,%3};"
        : "+f"(d[0]), "+f"(d[1]), "+f"(d[2]), "+f"(d[3])
        : "r"(a[0]), "r"(a[1]), "r"(a[2]), "r"(a[3]), "r"(b[0]), "r"(b[1]));
}

__device__ __forceinline__ void cp16(unsigned dst, const void* src) {
    asm volatile("cp.async.cg.shared.global [%0], [%1], 16;" :: "r"(dst), "l"(src));
}
__device__ __forceinline__ void cp_commit() { asm volatile("cp.async.commit_group;"); }
__device__ __forceinline__ void cp_wait0() { asm volatile("cp.async.wait_group 0;"); }
__device__ __forceinline__ void cp_wait1() { asm volatile("cp.async.wait_group 1;"); }

__device__ __forceinline__ float blockSum128(float v, float* sh) {
    #pragma unroll
    for (int o = 16; o; o >>= 1) v += __shfl_xor_sync(0xffffffffu, v, o);
    if ((threadIdx.x & 31) == 0) sh[threadIdx.x >> 5] = v;
    __syncthreads();
    float r = sh[0] + sh[1] + sh[2] + sh[3];
    __syncthreads();
    return r;
}

__device__ __forceinline__ float hw_elem(int r, int k,
    const float* rkW, const float* rbW, const float* rgW,
    const float* wkW, const float* wbW, const float* wgW,
    const float* erW, const float* adW) {
    if (k >= CQ || r >= 516) return 0.0f;
    if (r < 128) return rkW[r * CQ + k];
    if (r == 128) return rbW[k];
    if (r == 129) return rgW[k];
    if (r < 258) return wkW[(r - 130) * CQ + k];
    if (r == 258) return wbW[k];
    if (r == 259) return wgW[k];
    if (r < 388) return erW[(r - 260) * CQ + k];
    return adW[(r - 388) * CQ + k];
}

__device__ __forceinline__ float hb_elem(int r,
    const float* rkb, const float* rbb, const float* rgb,
    const float* wkb, const float* wbb, const float* wgb,
    const float* erb, const float* adb) {
    if (r < 128) return rkb[r];
    if (r == 128) return rbb[0];
    if (r == 129) return rgb[0];
    if (r < 258) return wkb[r - 130];
    if (r == 258) return wbb[0];
    if (r == 259) return wgb[0];
    if (r < 388) return erb[r - 260];
    if (r < 516) return adb[r - 388];
    return 0.0f;
}

// ---------------- prologue (5 launches total) ----------------
// 1) fused weight packing
__global__ void k_setup(const float* __restrict__ Wih, const float* __restrict__ Whh,
                        const float* __restrict__ bih, const float* __restrict__ bhh,
                        const float* __restrict__ Wout,
                        const float* rkW, const float* rbW, const float* rgW,
                        const float* wkW, const float* wbW, const float* wgW,
                        const float* erW, const float* adW) {
    long long i = (long long)blockIdx.x * blockDim.x + threadIdx.x;
    const long long NA = (long long)G4 * INQ;
    const long long NB = (long long)G4 * KR;
    const long long ND = (long long)CP * HQ;
    const long long NE = (long long)HRP * CP;
    if (i < NA) {
        int r = (int)(i / INQ);
        int k = (int)(i % INQ);
        int src = (r & 3) * HQ + (r >> 2);
        sc_WcatX[i] = Wih[src * (INQ + WQ) + k];
        return;
    }
    i -= NA;
    if (i < NB) {
        int r = (int)(i / KR);
        int k = (int)(i % KR);
        int src = (r & 3) * HQ + (r >> 2);
        float v = (k < WQ) ? Wih[src * (INQ + WQ) + INQ + k] : Whh[src * HQ + (k - WQ)];
        __nv_bfloat16 h, l;
        bsplit(v, &h, &l);
        sc_WrH[i] = h;
        sc_WrL[i] = l;
        return;
    }
    i -= NB;
    if (i < G4) {
        int r = (int)i;
        int src = (r & 3) * HQ + (r >> 2);
        sc_bg[r] = bih[src] + bhh[src];
        return;
    }
    i -= G4;
    if (i < ND) {
        int r = (int)(i / HQ);
        sc_WoutP[i] = (r < CQ) ? Wout[(long long)r * HQ + (i % HQ)] : 0.0f;
        return;
    }
    i -= ND;
    if (i < NE) {
        int r = (int)(i / CP);
        int k = (int)(i % CP);
        sc_HW[i] = hw_elem(r, k, rkW, rbW, rgW, wkW, wbW, wgW, erW, adW);
        return;
    }
}

// 2) memory copy + norms + bf16 split + state init
__global__ __launch_bounds__(256) void k_initmem(const float* __restrict__ memory) {
    if (blockIdx.x < 2048) {
        int row = blockIdx.x * 8 + (threadIdx.x >> 5);
        int lane = threadIdx.x & 31;
        const float* src = memory + (long long)row * WQ;
        float v[4];
        float s = 0.f;
        #pragma unroll
        for (int i = 0; i < 4; i++) { v[i] = src[lane + 32 * i]; s += v[i] * v[i]; }
        #pragma unroll
        for (int o = 16; o; o >>= 1) s += __shfl_xor_sync(0xffffffffu, s, o);
        float inv = 1.0f / fmaxf(sqrtf(s), 1e-12f);
        #pragma unroll
        for (int i = 0; i < 4; i++) {
            long long o = (long long)row * WQ + lane + 32 * i;
            sc_mem[o] = v[i];
            __nv_bfloat16 h, l;
            bsplit(v[i] * inv, &h, &l);
            sc_memnH[o] = h;
            sc_memnL[o] = l;
        }
    } else {
        long long base = (long long)(blockIdx.x - 2048) * 256 + threadIdx.x;
        if (base < (long long)BQ * NQ) { sc_rw[base] = 1.0f / (float)NQ; return; }
        base -= (long long)BQ * NQ;
        if (base < BQ * HQ) { sc_h[base] = 0.0f; return; }
        base -= BQ * HQ;
        if (base < BQ * HQ) { sc_c[base] = 0.0f; return; }
        base -= BQ * HQ;
        if (base < BQ * KR / 2) { ((unsigned*)sc_AH)[base] = 0u; return; }
        base -= BQ * KR / 2;
        if (base < BQ * KR / 2) { ((unsigned*)sc_AL)[base] = 0u; return; }
    }
}

// 3) folded biases (reads original arrays only)
__global__ __launch_bounds__(128) void k_biases(const float* bout, const float* pW, const float* pb,
    const float* rkW, const float* rbW, const float* rgW,
    const float* wkW, const float* wbW, const float* wgW,
    const float* erW, const float* adW,
    const float* rkb, const float* rbb, const float* rgb,
    const float* wkb, const float* wbb, const float* wgb,
    const float* erb, const float* adb) {
    __shared__ float sh[4];
    int r = blockIdx.x;
    int t = threadIdx.x;
    float s = 0.f;
    if (r < HRP) {
        for (int c = t; c < CQ; c += 128)
            s += hw_elem(r, c, rkW, rbW, rgW, wkW, wbW, wgW, erW, adW) * bout[c];
        s = blockSum128(s, sh);
        if (t == 0) sc_HOb[r] = s + hb_elem(r, rkb, rbb, rgb, wkb, wbb, wgb, erb, adb);
    } else {
        int o = r - HRP;
        for (int c = t; c < OUTQ; c += 128) s += pW[o * OUTQ + c] * bout[c];
        s = blockSum128(s, sh);
        if (t == 0) sc_HOb[r] = s + pb[o];
    }
}

// 4) xg = x @ Wih_x^T for all steps
__global__ __launch_bounds__(256) void k_xg(const float* __restrict__ x) {
    __shared__ float As[16][68];
    __shared__ float Bs[16][68];
    int tid = threadIdx.x;
    int n0 = blockIdx.x * 64;
    int m0 = blockIdx.y * 64;
    int rowL = tid >> 2;
    int k4 = (tid & 3) * 4;
    int txm = tid & 15;
    int txn = tid >> 4;
    float acc[4][4] = {};
    int m = m0 + rowL;
    const float* arow = x + ((long long)(m & 127) * SQ + (m >> 7)) * INQ;
    const float* brow = sc_WcatX + (long long)(n0 + rowL) * INQ;
    for (int k0 = 0; k0 < INQ; k0 += 16) {
        float4 a = *(const float4*)(arow + k0 + k4);
        float4 b = *(const float4*)(brow + k0 + k4);
        As[k4 + 0][rowL] = a.x; As[k4 + 1][rowL] = a.y; As[k4 + 2][rowL] = a.z; As[k4 + 3][rowL] = a.w;
        Bs[k4 + 0][rowL] = b.x; Bs[k4 + 1][rowL] = b.y; Bs[k4 + 2][rowL] = b.z; Bs[k4 + 3][rowL] = b.w;
        __syncthreads();
        #pragma unroll
        for (int k = 0; k < 16; k++) {
            float4 av = *(const float4*)&As[k][txm * 4];
            float4 bv = *(const float4*)&Bs[k][txn * 4];
            float aa[4] = {av.x, av.y, av.z, av.w};
            float bb[4] = {bv.x, bv.y, bv.z, bv.w};
            #pragma unroll
            for (int i = 0; i < 4; i++) {
                #pragma unroll
                for (int j = 0; j < 4; j++) acc[i][j] = fmaf(aa[i], bb[j], acc[i][j]);
            }
        }
        __syncthreads();
    }
    #pragma unroll
    for (int i = 0; i < 4; i++) {
        long long mi = m0 + txm * 4 + i;
        #pragma unroll
        for (int j = 0; j < 4; j++)
            sc_xg[mi * G4 + n0 + txn * 4 + j] = acc[i][j];
    }
}

// 5) HOW fold
__global__ __launch_bounds__(256) void k_fold(const float* __restrict__ pW,
                                              const float* __restrict__ Wout) {
    __shared__ float As[32][36];
    __shared__ float Bs[32][36];
    int tid = threadIdx.x;
    int n0 = blockIdx.x * 32;
    int second = (blockIdx.y >= 18) ? 1 : 0;
    int m0 = second ? (blockIdx.y - 18) * 32 : blockIdx.y * 32;
    const float* A = second ? pW : sc_HW;
    const float* B = second ? Wout : sc_WoutP;
    int lda = second ? OUTQ : CP;
    int K = second ? OUTQ : CP;
    int dstRow = second ? HRP : 0;
    int rowL = tid >> 3;
    int k4 = (tid & 7) * 4;
    int tm = tid & 7;
    int tn = tid >> 3;
    float acc[4] = {};
    for (int k0 = 0; k0 < K; k0 += 32) {
        float4 a = *(const float4*)(A + (long long)(m0 + rowL) * lda + k0 + k4);
        float4 b = *(const float4*)(B + (long long)(k0 + rowL) * HQ + n0 + k4);
        As[rowL][k4 + 0] = a.x; As[rowL][k4 + 1] = a.y; As[rowL][k4 + 2] = a.z; As[rowL][k4 + 3] = a.w;
        Bs[rowL][k4 + 0] = b.x; Bs[rowL][k4 + 1] = b.y; Bs[rowL][k4 + 2] = b.z; Bs[rowL][k4 + 3] = b.w;
        __syncthreads();
        #pragma unroll
        for (int k = 0; k < 32; k++) {
            float bv = Bs[k][tn];
            #pragma unroll
            for (int i = 0; i < 4; i++) acc[i] = fmaf(As[tm * 4 + i][k], bv, acc[i]);
        }
        __syncthreads();
    }
    #pragma unroll
    for (int i = 0; i < 4; i++)
        sc_HOW[(long long)(dstRow + m0 + tm * 4 + i) * HQ + n0 + tn] = acc[i];
}

// ---------------- LSTM recurrent GEMM: double-buffered cp.async + bf16 3-pass MMA ----------------
// grid (32, 1, 3): block = [128m x 128n], K-slice 384, chunks of 64 (6 chunks)
// smem buffer: AH/AL/BH/BL each 128 rows x 72 halfwords (144 B/row); buffer 73728 B, x2
__device__ __forceinline__ void lstm_stage(char* dsm, int buf, int c, int n0, int kbase, int tid) {
    for (int u = tid; u < 4096; u += 256) {
        int seg = u >> 10;
        int rem = u & 1023;
        int row = rem >> 3;
        int unit = rem & 7;
        unsigned dst = sptr(dsm + buf * 73728 + seg * 18432 + row * 144 + unit * 16);
        long long khw = (long long)kbase + c * 64 + unit * 8;
        const char* src;
        if (seg == 0)      src = (const char*)sc_AH  + ((long long)row * KR + khw) * 2;
        else if (seg == 1) src = (const char*)sc_AL  + ((long long)row * KR + khw) * 2;
        else if (seg == 2) src = (const char*)sc_WrH + ((long long)(n0 + row) * KR + khw) * 2;
        else               src = (const char*)sc_WrL + ((long long)(n0 + row) * KR + khw) * 2;
        cp16(dst, src);
    }
    cp_commit();
}

__global__ __launch_bounds__(256, 1) void k_lstm_mma() {
    extern __shared__ char dsm[];
    int tid = threadIdx.x;
    int w = tid >> 5;
    int lane = tid & 31;
    int n0 = blockIdx.x * 128;
    int z = blockIdx.z;
    int kbase = z * 384;
    int mBase = (w >> 2) * 64;
    int nBase = (w & 3) * 32;
    float acc[4][4][4] = {};
    lstm_stage(dsm, 0, 0, n0, kbase, tid);
    for (int c = 0; c < 6; c++) {
        if (c < 5) {
            lstm_stage(dsm, (c + 1) & 1, c + 1, n0, kbase, tid);
            cp_wait1();
        } else {
            cp_wait0();
        }
        __syncthreads();
        char* B0 = dsm + (c & 1) * 73728;
        __nv_bfloat16* AHs = (__nv_bfloat16*)B0;
        __nv_bfloat16* ALs = (__nv_bfloat16*)(B0 + 18432);
        __nv_bfloat16* BHs = (__nv_bfloat16*)(B0 + 36864);
        __nv_bfloat16* BLs = (__nv_bfloat16*)(B0 + 55296);
        #pragma unroll
        for (int kk = 0; kk < 4; kk++) {
            unsigned ah[4][4];
            unsigned al[4][4];
            int acol = kk * 16 + (lane >> 4) * 8;
            #pragma unroll
            for (int mt = 0; mt < 4; mt++) {
                int ar = mBase + mt * 16 + (lane & 15);
                ldm_x4(ah[mt], sptr(AHs + ar * 72 + acol));
                ldm_x4(al[mt], sptr(ALs + ar * 72 + acol));
            }
            int q = lane & 15;
            int bcol = kk * 16 + (q >> 3) * 8;
            #pragma unroll
            for (int nt = 0; nt < 4; nt++) {
                int br = nBase + nt * 8 + (q & 7);
                unsigned bh[2];
                unsigned bl[2];
                ldm_x2(bh, sptr(BHs + br * 72 + bcol));
                ldm_x2(bl, sptr(BLs + br * 72 + bcol));
                #pragma unroll
                for (int mt = 0; mt < 4; mt++) {
                    mma_bf16(acc[mt][nt], ah[mt], bh);
                    mma_bf16(acc[mt][nt], ah[mt], bl);
                    mma_bf16(acc[mt][nt], al[mt], bh);
                }
            }
        }
        __syncthreads();
    }
    float* dst = sc_g3 + (long long)z * BQ * G4;
    #pragma unroll
    for (int mt = 0; mt < 4; mt++) {
        int r = mBase + mt * 16 + (lane >> 2);
        #pragma unroll
        for (int nt = 0; nt < 4; nt++) {
            int cc = n0 + nBase + nt * 8 + (lane & 3) * 2;
            *(float2*)&dst[(long long)r * G4 + cc] = make_float2(acc[mt][nt][0], acc[mt][nt][1]);
            *(float2*)&dst[(long long)(r + 8) * G4 + cc] = make_float2(acc[mt][nt][2], acc[mt][nt][3]);
        }
    }
}

// ---------------- sim GEMM: K=128 fully resident + bf16 3-pass MMA ----------------
// grid (128, 2): block = [128m x 128n], K=128. smem: AH/AL/BH/BL 128 x 136 hw (272 B/row)
__global__ __launch_bounds__(256, 1) void k_sim_mma() {
    extern __shared__ char dsm[];
    __nv_bfloat16* AHs = (__nv_bfloat16*)dsm;
    __nv_bfloat16* ALs = (__nv_bfloat16*)(dsm + 34816);
    __nv_bfloat16* BHs = (__nv_bfloat16*)(dsm + 69632);
    __nv_bfloat16* BLs = (__nv_bfloat16*)(dsm + 104448);
    int tid = threadIdx.x;
    int w = tid >> 5;
    int lane = tid & 31;
    int n0 = blockIdx.x * 128;
    int m0 = blockIdx.y * 128;
    for (int u = tid; u < 8192; u += 256) {
        int seg = u >> 11;
        int rem = u & 2047;
        int row = rem >> 4;
        int unit = rem & 15;
        unsigned dst = sptr(dsm + seg * 34816 + row * 272 + unit * 16);
        const char* src;
        if (seg == 0)      src = (const char*)sc_keysH + ((long long)(m0 + row) * WQ + unit * 8) * 2;
        else if (seg == 1) src = (const char*)sc_keysL + ((long long)(m0 + row) * WQ + unit * 8) * 2;
        else if (seg == 2) src = (const char*)sc_memnH + ((long long)(n0 + row) * WQ + unit * 8) * 2;
        else               src = (const char*)sc_memnL + ((long long)(n0 + row) * WQ + unit * 8) * 2;
        cp16(dst, src);
    }
    cp_commit();
    cp_wait0();
    __syncthreads();
    int mBase = (w >> 2) * 64;
    int nBase = (w & 3) * 32;
    float acc[4][4][4] = {};
    #pragma unroll
    for (int kk = 0; kk < 8; kk++) {
        unsigned ah[4][4];
        unsigned al[4][4];
        int acol = kk * 16 + (lane >> 4) * 8;
        #pragma unroll
        for (int mt = 0; mt < 4; mt++) {
            int ar = mBase + mt * 16 + (lane & 15);
            ldm_x4(ah[mt], sptr(AHs + ar * 136 + acol));
            ldm_x4(al[mt], sptr(ALs + ar * 136 + acol));
        }
        int q = lane & 15;
        int bcol = kk * 16 + (q >> 3) * 8;
        #pragma unroll
        for (int nt = 0; nt < 4; nt++) {
            int br = nBase + nt * 8 + (q & 7);
            unsigned bh[2];
            unsigned bl[2];
            ldm_x2(bh, sptr(BHs + br * 136 + bcol));
            ldm_x2(bl, sptr(BLs + br * 136 + bcol));
            #pragma unroll
            for (int mt = 0; mt < 4; mt++) {
                mma_bf16(acc[mt][nt], ah[mt], bh);
                mma_bf16(acc[mt][nt], ah[mt], bl);
                mma_bf16(acc[mt][nt], al[mt], bh);
            }
        }
    }
    #pragma unroll
    for (int mt = 0; mt < 4; mt++) {
        int r = m0 + mBase + mt * 16 + (lane >> 2);
        #pragma unroll
        for (int nt = 0; nt < 4; nt++) {
            int cc = n0 + nBase + nt * 8 + (lane & 3) * 2;
            *(float2*)&sc_sim[(long long)r * NQ + cc] = make_float2(acc[mt][nt][0], acc[mt][nt][1]);
            *(float2*)&sc_sim[(long long)(r + 8) * NQ + cc] = make_float2(acc[mt][nt][2], acc[mt][nt][3]);
        }
    }
}

// ---------------- remaining per-step kernels (validated round 7) ----------------
__global__ __launch_bounds__(256) void k_gates(int s) {
    int idx = blockIdx.x * blockDim.x + threadIdx.x;
    if (idx >= BQ * HQ) return;
    int b = idx >> 10;
    int u = idx & 1023;
    long long off = (long long)b * G4 + u * 4;
    float4 p0 = *(const float4*)&sc_g3[off];
    float4 p1 = *(const float4*)&sc_g3[(long long)BQ * G4 + off];
    float4 p2 = *(const float4*)&sc_g3[(long long)2 * BQ * G4 + off];
    float4 xg = *(const float4*)&sc_xg[((long long)s * BQ + b) * G4 + u * 4];
    float4 bg = *(const float4*)&sc_bg[u * 4];
    float i_ = p0.x + p1.x + p2.x + xg.x + bg.x;
    float f_ = p0.y + p1.y + p2.y + xg.y + bg.y;
    float g_ = p0.z + p1.z + p2.z + xg.z + bg.z;
    float o_ = p0.w + p1.w + p2.w + xg.w + bg.w;
    float c = sigmoidf_(f_) * sc_c[idx] + sigmoidf_(i_) * tanhf(g_);
    sc_c[idx] = c;
    float hv = sigmoidf_(o_) * tanhf(c);
    sc_h[idx] = hv;
    __nv_bfloat16 h;
    __nv_bfloat16 l;
    bsplit(hv, &h, &l);
    sc_AH[b * KR + WQ + u] = h;
    sc_AL[b * KR + WQ + u] = l;
}

__global__ __launch_bounds__(256) void k_headsout(float* __restrict__ out, int s) {
    __shared__ float As[32][33];
    __shared__ float Bs[32][33];
    int tid = threadIdx.x;
    int n0 = blockIdx.x * 32;
    int m0 = blockIdx.y * 32;
    int rowL = tid >> 3;
    int k4 = (tid & 7) * 4;
    int tm = tid & 7;
    int tn = tid >> 3;
    float acc[4] = {};
    for (int k0 = 0; k0 < HQ; k0 += 32) {
        float4 a = *(const float4*)(sc_h + (long long)(m0 + rowL) * HQ + k0 + k4);
        float4 b = *(const float4*)(sc_HOW + (long long)(n0 + rowL) * HQ + k0 + k4);
        As[rowL][k4 + 0] = a.x; As[rowL][k4 + 1] = a.y; As[rowL][k4 + 2] = a.z; As[rowL][k4 + 3] = a.w;
        Bs[rowL][k4 + 0] = b.x; Bs[rowL][k4 + 1] = b.y; Bs[rowL][k4 + 2] = b.z; Bs[rowL][k4 + 3] = b.w;
        __syncthreads();
        #pragma unroll
        for (int k = 0; k < 32; k++) {
            float bv = Bs[tn][k];
            #pragma unroll
            for (int i = 0; i < 4; i++) acc[i] = fmaf(As[tm * 4 + i][k], bv, acc[i]);
        }
        __syncthreads();
    }
    int n = n0 + tn;
    float bb = sc_HOb[n];
    #pragma unroll
    for (int i = 0; i < 4; i++) {
        int m = m0 + tm * 4 + i;
        float v = acc[i] + bb;
        if (n < HRP) sc_heads[m * HRP + n] = v;
        else out[((long long)m * SQ + s) * OUTQ + (n - HRP)] = v;
    }
}

__global__ __launch_bounds__(128) void k_headproc() {
    __shared__ float sh[4];
    int b = blockIdx.x;
    int w = threadIdx.x;
    const float* hd = sc_heads + b * HRP;
    float rk = hd[w];
    float wk = hd[130 + w];
    float nr2 = blockSum128(rk * rk, sh);
    float nw2 = blockSum128(wk * wk, sh);
    __nv_bfloat16 h;
    __nv_bfloat16 l;
    bsplit(rk / fmaxf(sqrtf(nr2), 1e-12f), &h, &l);
    sc_keysH[b * WQ + w] = h;
    sc_keysL[b * WQ + w] = l;
    bsplit(wk / fmaxf(sqrtf(nw2), 1e-12f), &h, &l);
    sc_keysH[(128 + b) * WQ + w] = h;
    sc_keysL[(128 + b) * WQ + w] = l;
    if (w == 0) {
        sc_beta[b] = softplusf_(hd[128]);
        sc_gamma[b] = 1.0f + softplusf_(hd[129]);
        sc_beta[128 + b] = softplusf_(hd[258]);
        sc_gamma[128 + b] = 1.0f + softplusf_(hd[259]);
    }
    sc_er[b * WQ + w] = sigmoidf_(hd[260 + w]);
    sc_ad[b * WQ + w] = tanhf(hd[388 + w]);
}

__global__ __launch_bounds__(512) void k_softmax512() {
    __shared__ float sh[16];
    __shared__ float bcv;
    int q = blockIdx.x;
    int tid = threadIdx.x;
    int lane = tid & 31;
    int wid = tid >> 5;
    float beta = sc_beta[q];
    float gamma = sc_gamma[q];
    const float* row = sc_sim + (long long)q * NQ;
    float v[32];
    float mx = -1e30f;
    #pragma unroll
    for (int i = 0; i < 32; i++) { v[i] = row[tid + i * 512]; mx = fmaxf(mx, v[i]); }
    #pragma unroll
    for (int o = 16; o; o >>= 1) mx = fmaxf(mx, __shfl_xor_sync(0xffffffffu, mx, o));
    if (lane == 0) sh[wid] = mx;
    __syncthreads();
    if (tid == 0) {
        float m = sh[0];
        #pragma unroll
        for (int i = 1; i < 16; i++) m = fmaxf(m, sh[i]);
        bcv = m;
    }
    __syncthreads();
    mx = bcv;
    float s = 0.f;
    #pragma unroll
    for (int i = 0; i < 32; i++) { v[i] = __expf(beta * (v[i] - mx)); s += v[i]; }
    __syncthreads();
    #pragma unroll
    for (int o = 16; o; o >>= 1) s += __shfl_xor_sync(0xffffffffu, s, o);
    if (lane == 0) sh[wid] = s;
    __syncthreads();
    if (tid == 0) {
        float t = 0.f;
        #pragma unroll
        for (int i = 0; i < 16; i++) t += sh[i];
        bcv = 1.0f / t;
    }
    __syncthreads();
    float inv = bcv;
    if (q < 128) {
        float* rw = sc_rw + (long long)q * NQ;
        #pragma unroll
        for (int i = 0; i < 32; i++) {
            int n = tid + i * 512;
            rw[n] = gamma * (v[i] * inv) + (1.0f - gamma) * rw[n];
        }
    } else {
        float* ww = sc_ww + (long long)(q - 128) * NQ;
        float u = (1.0f - gamma) * (1.0f / (float)NQ);
        #pragma unroll
        for (int i = 0; i < 32; i++) {
            ww[tid + i * 512] = gamma * (v[i] * inv) + u;
        }
    }
}

__global__ __launch_bounds__(256) void k_memupd_rv() {
    __shared__ __align__(16) float mns[64][132];
    __shared__ __align__(16) float ubuf[2656];
    __shared__ float rowsq[64][4];
    __shared__ float sInv[64];
    float (*sw)[68] = (float(*)[68])ubuf;
    float (*se)[132] = (float(*)[132])(ubuf + 8 * 68);
    float (*sa)[132] = (float(*)[132])(ubuf + 8 * 68 + 8 * 132);
    float (*srw)[132] = (float(*)[132])ubuf;
    int tid = threadIdx.x;
    int n0 = blockIdx.x * 64;
    int txn = tid & 15;
    int txw = tid >> 4;
    float ae[4][8] = {};
    float aa[4][8] = {};
    for (int b0 = 0; b0 < BQ; b0 += 8) {
        int kk = tid >> 5;
        int half = tid & 31;
        *(float2*)&sw[kk][half * 2] = *(const float2*)&sc_ww[(long long)(b0 + kk) * NQ + n0 + half * 2];
        *(float4*)&se[kk][half * 4] = *(const float4*)&sc_er[(b0 + kk) * WQ + half * 4];
        *(float4*)&sa[kk][half * 4] = *(const float4*)&sc_ad[(b0 + kk) * WQ + half * 4];
        __syncthreads();
        #pragma unroll
        for (int k = 0; k < 8; k++) {
            float4 w4 = *(const float4*)&sw[k][txn * 4];
            float4 e0 = *(const float4*)&se[k][txw * 8];
            float4 e1 = *(const float4*)&se[k][txw * 8 + 4];
            float4 a0 = *(const float4*)&sa[k][txw * 8];
            float4 a1 = *(const float4*)&sa[k][txw * 8 + 4];
            float wv[4] = {w4.x, w4.y, w4.z, w4.w};
            float ev[8] = {e0.x, e0.y, e0.z, e0.w, e1.x, e1.y, e1.z, e1.w};
            float av[8] = {a0.x, a0.y, a0.z, a0.w, a1.x, a1.y, a1.z, a1.w};
            #pragma unroll
            for (int i = 0; i < 4; i++) {
                #pragma unroll
                for (int j = 0; j < 8; j++) {
                    ae[i][j] = fmaf(wv[i], ev[j], ae[i][j]);
                    aa[i][j] = fmaf(wv[i], av[j], aa[i][j]);
                }
            }
        }
        __syncthreads();
    }
    #pragma unroll
    for (int i = 0; i < 4; i++) {
        int nl = txn * 4 + i;
        long long base = (long long)(n0 + nl) * WQ + txw * 8;
        float4 m0v = *(const float4*)&sc_mem[base];
        float4 m1v = *(const float4*)&sc_mem[base + 4];
        float r[8] = {m0v.x, m0v.y, m0v.z, m0v.w, m1v.x, m1v.y, m1v.z, m1v.w};
        #pragma unroll
        for (int j = 0; j < 8; j++) r[j] = r[j] * (1.0f - ae[i][j]) + aa[i][j];
        *(float4*)&sc_mem[base] = make_float4(r[0], r[1], r[2], r[3]);
        *(float4*)&sc_mem[base + 4] = make_float4(r[4], r[5], r[6], r[7]);
        *(float4*)&mns[nl][txw * 8] = make_float4(r[0], r[1], r[2], r[3]);
        *(float4*)&mns[nl][txw * 8 + 4] = make_float4(r[4], r[5], r[6], r[7]);
    }
    __syncthreads();
    {
        int r = tid >> 2;
        int qq = tid & 3;
        float s = 0.f;
        #pragma unroll
        for (int t = 0; t < 32; t += 4) {
            float4 v = *(const float4*)&mns[r][qq * 32 + t];
            s += v.x * v.x + v.y * v.y + v.z * v.z + v.w * v.w;
        }
        rowsq[r][qq] = s;
    }
    __syncthreads();
    if (tid < 64) {
        float s = rowsq[tid][0] + rowsq[tid][1] + rowsq[tid][2] + rowsq[tid][3];
        sInv[tid] = 1.0f / fmaxf(sqrtf(s), 1e-12f);
    }
    __syncthreads();
    for (int i = tid; i < 64 * 32; i += 256) {
        int r = i >> 5;
        int c = (i & 31) * 4;
        float inv = sInv[r];
        float4 v = *(const float4*)&mns[r][c];
        __nv_bfloat16 h0, l0, h1, l1, h2, l2, h3, l3;
        bsplit(v.x * inv, &h0, &l0);
        bsplit(v.y * inv, &h1, &l1);
        bsplit(v.z * inv, &h2, &l2);
        bsplit(v.w * inv, &h3, &l3);
        long long o = (long long)(n0 + r) * WQ + c;
        st_bf2(&sc_memnH[o], h0, h1);
        st_bf2(&sc_memnH[o + 2], h2, h3);
        st_bf2(&sc_memnL[o], l0, l1);
        st_bf2(&sc_memnL[o + 2], l2, l3);
    }
    int tb = tid & 15;
    int tw = tid >> 4;
    float racc[8][8] = {};
    for (int nc = 0; nc < 4; nc++) {
        __syncthreads();
        #pragma unroll
        for (int r = 0; r < 8; r++) {
            int b = tw + r * 16;
            srw[tb][b] = sc_rw[(long long)b * NQ + n0 + nc * 16 + tb];
        }
        __syncthreads();
        #pragma unroll
        for (int nn = 0; nn < 16; nn++) {
            float4 r0 = *(const float4*)&srw[nn][tb * 8];
            float4 r1 = *(const float4*)&srw[nn][tb * 8 + 4];
            int nl = nc * 16 + nn;
            float4 q0 = *(const float4*)&mns[nl][tw * 8];
            float4 q1 = *(const float4*)&mns[nl][tw * 8 + 4];
            float rb[8] = {r0.x, r0.y, r0.z, r0.w, r1.x, r1.y, r1.z, r1.w};
            float mw[8] = {q0.x, q0.y, q0.z, q0.w, q1.x, q1.y, q1.z, q1.w};
            #pragma unroll
            for (int i = 0; i < 8; i++) {
                #pragma unroll
                for (int j = 0; j < 8; j++) racc[i][j] = fmaf(rb[i], mw[j], racc[i][j]);
            }
        }
    }
    float* dst = sc_rvpart + (long long)blockIdx.x * BQ * WQ;
    #pragma unroll
    for (int i = 0; i < 8; i++) {
        int b = tb * 8 + i;
        *(float4*)&dst[b * WQ + tw * 8] = make_float4(racc[i][0], racc[i][1], racc[i][2], racc[i][3]);
        *(float4*)&dst[b * WQ + tw * 8 + 4] = make_float4(racc[i][4], racc[i][5], racc[i][6], racc[i][7]);
    }
}

__global__ __launch_bounds__(256) void k_rvreduce() {
    __shared__ float4 red[32][8];
    int tid = threadIdx.x;
    int outIdx = blockIdx.x * 32 + (tid >> 3);
    int sub = tid & 7;
    const float4* p = (const float4*)sc_rvpart;
    float4 s = make_float4(0.f, 0.f, 0.f, 0.f);
    #pragma unroll 4
    for (int i = 0; i < 32; i++) {
        float4 t = p[(long long)(sub + i * 8) * 4096 + outIdx];
        s.x += t.x; s.y += t.y; s.z += t.z; s.w += t.w;
    }
    red[tid >> 3][sub] = s;
    __syncthreads();
    if (sub == 0) {
        float4 a = make_float4(0.f, 0.f, 0.f, 0.f);
        #pragma unroll
        for (int i = 0; i < 8; i++) {
            float4 t = red[tid >> 3][i];
            a.x += t.x; a.y += t.y; a.z += t.z; a.w += t.w;
        }
        int b = outIdx >> 5;
        int c0 = (outIdx & 31) * 4;
        __nv_bfloat16 h0, l0, h1, l1, h2, l2, h3, l3;
        bsplit(a.x, &h0, &l0);
        bsplit(a.y, &h1, &l1);
        bsplit(a.z, &h2, &l2);
        bsplit(a.w, &h3, &l3);
        int o = b * KR + c0;
        st_bf2(&sc_AH[o], h0, h1);
        st_bf2(&sc_AH[o + 2], h2, h3);
        st_bf2(&sc_AL[o], l0, l1);
        st_bf2(&sc_AL[o + 2], l2, l3);
    }
}

// ---------------- host launcher ----------------
extern "C" void kernel_launch(void* const* d_in, const int* in_sizes, int n_in,
                              void* d_out, int out_size) {
    const float* x = (const float*)d_in[0];
    const float* memory = (const float*)d_in[1];
    const float* Wih = (const float*)d_in[2];
    const float* Whh = (const float*)d_in[3];
    const float* bih = (const float*)d_in[4];
    const float* bhh = (const float*)d_in[5];
    const float* Wout = (const float*)d_in[6];
    const float* bout = (const float*)d_in[7];
    const float* rkW = (const float*)d_in[8];
    const float* rkb = (const float*)d_in[9];
    const float* rbW = (const float*)d_in[10];
    const float* rbb = (const float*)d_in[11];
    const float* rgW = (const float*)d_in[12];
    const float* rgb = (const float*)d_in[13];
    const float* wkW = (const float*)d_in[14];
    const float* wkb = (const float*)d_in[15];
    const float* wbW = (const float*)d_in[16];
    const float* wbb = (const float*)d_in[17];
    const float* wgW = (const float*)d_in[18];
    const float* wgb = (const float*)d_in[19];
    const float* erW = (const float*)d_in[20];
    const float* erb = (const float*)d_in[21];
    const float* adW = (const float*)d_in[22];
    const float* adb = (const float*)d_in[23];
    const float* pW = (const float*)d_in[24];
    const float* pb = (const float*)d_in[25];
    float* out = (float*)d_out;

    cudaFuncSetAttribute(k_lstm_mma, cudaFuncAttributeMaxDynamicSharedMemorySize, 147456);
    cudaFuncSetAttribute(k_sim_mma, cudaFuncAttributeMaxDynamicSharedMemorySize, 139264);

    // prologue: exactly 5 launches (so ncu -s 5 captures k_lstm_mma)
    long long setup_total = (long long)G4 * INQ + (long long)G4 * KR + G4 +
                            (long long)CP * HQ + (long long)HRP * CP;
    k_setup<<<(int)((setup_total + 255) / 256), 256>>>(Wih, Whh, bih, bhh, Wout,
                                                       rkW, rbW, rgW, wkW, wbW, wgW, erW, adW);
    k_initmem<<<2048 + 9792, 256>>>(memory);
    k_biases<<<HOW, 128>>>(bout, pW, pb, rkW, rbW, rgW, wkW, wbW, wgW, erW, adW,
                           rkb, rbb, rgb, wkb, wbb, wgb, erb, adb);
    k_xg<<<dim3(G4 / 64, MQ / 64), 256>>>(x);
    k_fold<<<dim3(HQ / 32, 34), 256>>>(pW, Wout);

    for (int s = 0; s < SQ; s++) {
        k_lstm_mma<<<dim3(G4 / 128, 1, 3), 256, 147456>>>();
        k_gates<<<(BQ * HQ + 255) / 256, 256>>>(s);
        k_headsout<<<dim3(HOW / 32, BQ / 32), 256>>>(out, s);
        k_headproc<<<BQ, 128>>>();
        k_sim_mma<<<dim3(NQ / 128, 2), 256, 139264>>>();
        k_softmax512<<<2 * BQ, 512>>>();
        k_memupd_rv<<<NQ / 64, 256>>>();
        k_rvreduce<<<128, 256>>>();
    }
}

// round 9
// speedup vs baseline: 1.4192x; 1.0654x over previous
#include <cuda_runtime.h>
#include <cuda_bf16.h>
#include <math.h>

#define BQ   128
#define SQ   32
#define INQ  512
#define HQ   1024
#define OUTQ 512
#define NQ   16384
#define WQ   128
#define CQ   899
#define CP   960
#define K1   1664
#define KR   1152
#define G4   4096
#define HRP  576
#define HOW  1088
#define NCHUNK 256
#define NZ   4            // LSTM split-K ways
#define KSLC 416          // K per slice (halfwords)

// ---------------- device globals ----------------
__device__ float sc_mem[NQ * WQ];
__device__ __nv_bfloat16 sc_WfH[(long long)G4 * K1];   // full gate-interleaved Wcat hi
__device__ __nv_bfloat16 sc_WfL[(long long)G4 * K1];   // lo
__device__ __nv_bfloat16 sc_xH[(long long)SQ * BQ * INQ]; // x bf16 hi, [s][b][k]
__device__ __nv_bfloat16 sc_xL[(long long)SQ * BQ * INQ];
__device__ float sc_bg[G4];
__device__ float sc_WoutP[CP * HQ];
__device__ float sc_HW[HRP * CP];
__device__ float sc_HOW[HOW * HQ];
__device__ float sc_HOb[HOW];
__device__ float sc_g4[NZ * BQ * G4];
__device__ float sc_h[BQ * HQ];
__device__ float sc_c[BQ * HQ];
__device__ __nv_bfloat16 sc_AH[BQ * KR];   // [rv|h] bf16 hi
__device__ __nv_bfloat16 sc_AL[BQ * KR];
__device__ float sc_rw[BQ * NQ];
__device__ float sc_ww[BQ * NQ];
__device__ float sc_heads[BQ * HRP];
__device__ __nv_bfloat16 sc_keysH[2 * BQ * WQ];
__device__ __nv_bfloat16 sc_keysL[2 * BQ * WQ];
__device__ __nv_bfloat16 sc_memnH[NQ * WQ];
__device__ __nv_bfloat16 sc_memnL[NQ * WQ];
__device__ float sc_beta[2 * BQ];
__device__ float sc_gamma[2 * BQ];
__device__ float sc_er[BQ * WQ];
__device__ float sc_ad[BQ * WQ];
__device__ float sc_sim[2 * BQ * NQ];
__device__ float sc_rvpart[NCHUNK * BQ * WQ];

// ---------------- helpers ----------------
__device__ __forceinline__ float sigmoidf_(float x) { return 1.0f / (1.0f + expf(-x)); }
__device__ __forceinline__ float softplusf_(float x) { return x > 20.0f ? x : log1pf(expf(x)); }

__device__ __forceinline__ void bsplit(float v, __nv_bfloat16* h, __nv_bfloat16* l) {
    __nv_bfloat16 hi = __float2bfloat16(v);
    *h = hi;
    *l = __float2bfloat16(v - __bfloat162float(hi));
}

__device__ __forceinline__ void st_bf2(__nv_bfloat16* p, __nv_bfloat16 a, __nv_bfloat16 b) {
    __nv_bfloat162 t;
    t.x = a;
    t.y = b;
    *(__nv_bfloat162*)p = t;
}

__device__ __forceinline__ unsigned sptr(const void* p) {
    return (unsigned)__cvta_generic_to_shared(p);
}

__device__ __forceinline__ void ldm_x4(unsigned* r, unsigned a) {
    asm volatile("ldmatrix.sync.aligned.m8n8.x4.shared.b16 {%0,%1,%2,%3}, [%4];"
        : "=r"(r[0]), "=r"(r[1]), "=r"(r[2]), "=r"(r[3]) : "r"(a));
}

__device__ __forceinline__ void ldm_x2(unsigned* r, unsigned a) {
    asm volatile("ldmatrix.sync.aligned.m8n8.x2.shared.b16 {%0,%1}, [%2];"
        : "=r"(r[0]), "=r"(r[1]) : "r"(a));
}

__device__ __forceinline__ void mma_bf16(float* d, const unsigned* a, const unsigned* b) {
    asm volatile("mma.sync.aligned.m16n8k16.row.col.f32.bf16.bf16.f32 "
        "{%0,%1,%2,%3}, {%4,%5,%6,%7}, {%8,%9}, {%0,%1,%2,%3};"
        : "+f"(d[0]), "+f"(d[1]), "+f"(d[2]), "+f"(d[3])
        : "r"(a[0]), "r"(a[1]), "r"(a[2]), "r"(a[3]), "r"(b[0]), "r"(b[1]));
}

__device__ __forceinline__ void cp16(unsigned dst, const void* src) {
    asm volatile("cp.async.cg.shared.global [%0], [%1], 16;" :: "r"(dst), "l"(src));
}
__device__ __forceinline__ void cp_commit() { asm volatile("cp.async.commit_group;"); }
__device__ __forceinline__ void cp_wait0() { asm volatile("cp.async.wait_group 0;"); }
__device__ __forceinline__ void cp_wait1() { asm volatile("cp.async.wait_group 1;"); }

__device__ __forceinline__ float blockSum128(float v, float* sh) {
    #pragma unroll
    for (int o = 16; o; o >>= 1) v += __shfl_xor_sync(0xffffffffu, v, o);
    if ((threadIdx.x & 31) == 0) sh[threadIdx.x >> 5] = v;
    __syncthreads();
    float r = sh[0] + sh[1] + sh[2] + sh[3];
    __syncthreads();
    return r;
}

__device__ __forceinline__ float hw_elem(int r, int k,
    const float* rkW, const float* rbW, const float* rgW,
    const float* wkW, const float* wbW, const float* wgW,
    const float* erW, const float* adW) {
    if (k >= CQ || r >= 516) return 0.0f;
    if (r < 128) return rkW[r * CQ + k];
    if (r == 128) return rbW[k];
    if (r == 129) return rgW[k];
    if (r < 258) return wkW[(r - 130) * CQ + k];
    if (r == 258) return wbW[k];
    if (r == 259) return wgW[k];
    if (r < 388) return erW[(r - 260) * CQ + k];
    return adW[(r - 388) * CQ + k];
}

__device__ __forceinline__ float hb_elem(int r,
    const float* rkb, const float* rbb, const float* rgb,
    const float* wkb, const float* wbb, const float* wgb,
    const float* erb, const float* adb) {
    if (r < 128) return rkb[r];
    if (r == 128) return rbb[0];
    if (r == 129) return rgb[0];
    if (r < 258) return wkb[r - 130];
    if (r == 258) return wbb[0];
    if (r == 259) return wgb[0];
    if (r < 388) return erb[r - 260];
    if (r < 516) return adb[r - 388];
    return 0.0f;
}

// ---------------- prologue (5 launches) ----------------
// 1) weights packing: Wf (gate-interleaved, bf16 split), bg, WoutP, HW
__global__ void k_setup_w(const float* __restrict__ Wih, const float* __restrict__ Whh,
                          const float* __restrict__ bih, const float* __restrict__ bhh,
                          const float* __restrict__ Wout,
                          const float* rkW, const float* rbW, const float* rgW,
                          const float* wkW, const float* wbW, const float* wgW,
                          const float* erW, const float* adW) {
    long long i = (long long)blockIdx.x * blockDim.x + threadIdx.x;
    const long long NW = (long long)G4 * K1;
    const long long ND = (long long)CP * HQ;
    const long long NE = (long long)HRP * CP;
    if (i < NW) {
        int r = (int)(i / K1);
        int k = (int)(i % K1);
        int src = (r & 3) * HQ + (r >> 2);
        float v = (k < INQ + WQ) ? Wih[src * (INQ + WQ) + k] : Whh[src * HQ + (k - INQ - WQ)];
        __nv_bfloat16 h, l;
        bsplit(v, &h, &l);
        sc_WfH[i] = h;
        sc_WfL[i] = l;
        return;
    }
    i -= NW;
    if (i < G4) {
        int r = (int)i;
        int src = (r & 3) * HQ + (r >> 2);
        sc_bg[r] = bih[src] + bhh[src];
        return;
    }
    i -= G4;
    if (i < ND) {
        int r = (int)(i / HQ);
        sc_WoutP[i] = (r < CQ) ? Wout[(long long)r * HQ + (i % HQ)] : 0.0f;
        return;
    }
    i -= ND;
    if (i < NE) {
        int r = (int)(i / CP);
        int k = (int)(i % CP);
        sc_HW[i] = hw_elem(r, k, rkW, rbW, rgW, wkW, wbW, wgW, erW, adW);
        return;
    }
}

// 2) x bf16 split: sc_x[s][b][k] = bsplit(x[b][s][k])
__global__ void k_setup_x(const float* __restrict__ x) {
    long long i = (long long)blockIdx.x * blockDim.x + threadIdx.x;
    if (i >= (long long)SQ * BQ * INQ) return;
    int k = (int)(i % INQ);
    long long sb = i / INQ;
    int b = (int)(sb % BQ);
    int s = (int)(sb / BQ);
    float v = x[((long long)b * SQ + s) * INQ + k];
    __nv_bfloat16 h, l;
    bsplit(v, &h, &l);
    sc_xH[i] = h;
    sc_xL[i] = l;
}

// 3) memory copy + norms + bf16 split + state init
__global__ __launch_bounds__(256) void k_initmem(const float* __restrict__ memory) {
    if (blockIdx.x < 2048) {
        int row = blockIdx.x * 8 + (threadIdx.x >> 5);
        int lane = threadIdx.x & 31;
        const float* src = memory + (long long)row * WQ;
        float v[4];
        float s = 0.f;
        #pragma unroll
        for (int i = 0; i < 4; i++) { v[i] = src[lane + 32 * i]; s += v[i] * v[i]; }
        #pragma unroll
        for (int o = 16; o; o >>= 1) s += __shfl_xor_sync(0xffffffffu, s, o);
        float inv = 1.0f / fmaxf(sqrtf(s), 1e-12f);
        #pragma unroll
        for (int i = 0; i < 4; i++) {
            long long o = (long long)row * WQ + lane + 32 * i;
            sc_mem[o] = v[i];
            __nv_bfloat16 h, l;
            bsplit(v[i] * inv, &h, &l);
            sc_memnH[o] = h;
            sc_memnL[o] = l;
        }
    } else {
        long long base = (long long)(blockIdx.x - 2048) * 256 + threadIdx.x;
        if (base < (long long)BQ * NQ) { sc_rw[base] = 1.0f / (float)NQ; return; }
        base -= (long long)BQ * NQ;
        if (base < BQ * HQ) { sc_h[base] = 0.0f; return; }
        base -= BQ * HQ;
        if (base < BQ * HQ) { sc_c[base] = 0.0f; return; }
        base -= BQ * HQ;
        if (base < BQ * KR / 2) { ((unsigned*)sc_AH)[base] = 0u; return; }
        base -= BQ * KR / 2;
        if (base < BQ * KR / 2) { ((unsigned*)sc_AL)[base] = 0u; return; }
    }
}

// 4) folded biases
__global__ __launch_bounds__(128) void k_biases(const float* bout, const float* pW, const float* pb,
    const float* rkW, const float* rbW, const float* rgW,
    const float* wkW, const float* wbW, const float* wgW,
    const float* erW, const float* adW,
    const float* rkb, const float* rbb, const float* rgb,
    const float* wkb, const float* wbb, const float* wgb,
    const float* erb, const float* adb) {
    __shared__ float sh[4];
    int r = blockIdx.x;
    int t = threadIdx.x;
    float s = 0.f;
    if (r < HRP) {
        for (int c = t; c < CQ; c += 128)
            s += hw_elem(r, c, rkW, rbW, rgW, wkW, wbW, wgW, erW, adW) * bout[c];
        s = blockSum128(s, sh);
        if (t == 0) sc_HOb[r] = s + hb_elem(r, rkb, rbb, rgb, wkb, wbb, wgb, erb, adb);
    } else {
        int o = r - HRP;
        for (int c = t; c < OUTQ; c += 128) s += pW[o * OUTQ + c] * bout[c];
        s = blockSum128(s, sh);
        if (t == 0) sc_HOb[r] = s + pb[o];
    }
}

// 5) HOW fold
__global__ __launch_bounds__(256) void k_fold(const float* __restrict__ pW,
                                              const float* __restrict__ Wout) {
    __shared__ float As[32][36];
    __shared__ float Bs[32][36];
    int tid = threadIdx.x;
    int n0 = blockIdx.x * 32;
    int second = (blockIdx.y >= 18) ? 1 : 0;
    int m0 = second ? (blockIdx.y - 18) * 32 : blockIdx.y * 32;
    const float* A = second ? pW : sc_HW;
    const float* B = second ? Wout : sc_WoutP;
    int lda = second ? OUTQ : CP;
    int K = second ? OUTQ : CP;
    int dstRow = second ? HRP : 0;
    int rowL = tid >> 3;
    int k4 = (tid & 7) * 4;
    int tm = tid & 7;
    int tn = tid >> 3;
    float acc[4] = {};
    for (int k0 = 0; k0 < K; k0 += 32) {
        float4 a = *(const float4*)(A + (long long)(m0 + rowL) * lda + k0 + k4);
        float4 b = *(const float4*)(B + (long long)(k0 + rowL) * HQ + n0 + k4);
        As[rowL][k4 + 0] = a.x; As[rowL][k4 + 1] = a.y; As[rowL][k4 + 2] = a.z; As[rowL][k4 + 3] = a.w;
        Bs[rowL][k4 + 0] = b.x; Bs[rowL][k4 + 1] = b.y; Bs[rowL][k4 + 2] = b.z; Bs[rowL][k4 + 3] = b.w;
        __syncthreads();
        #pragma unroll
        for (int k = 0; k < 32; k++) {
            float bv = Bs[k][tn];
            #pragma unroll
            for (int i = 0; i < 4; i++) acc[i] = fmaf(As[tm * 4 + i][k], bv, acc[i]);
        }
        __syncthreads();
    }
    #pragma unroll
    for (int i = 0; i < 4; i++)
        sc_HOW[(long long)(dstRow + m0 + tm * 4 + i) * HQ + n0 + tn] = acc[i];
}

// ---------------- LSTM full GEMM (x folded in): K=1664, split-K 4, chunks of 32 ----------------
// smem per chunk buffer: 4 segs x 128 rows x 40 hw (80 B/row) = 40960 B; double buffered = 81920 B
#define L_ROWHW 40
#define L_SEGB  (128 * L_ROWHW * 2)
#define L_BUFB  (4 * L_SEGB)

__device__ __forceinline__ void lstm_stage(char* dsm, int buf, int c, int n0, int kbase, int s, int tid) {
    for (int u = tid; u < 2048; u += 256) {
        int seg = u >> 9;
        int rem = u & 511;
        int row = rem >> 2;
        int unit = rem & 3;
        unsigned dst = sptr(dsm + buf * L_BUFB + seg * L_SEGB + row * (L_ROWHW * 2) + unit * 16);
        int kk = kbase + c * 32 + unit * 8;   // global k in halfwords, 0..1663
        const char* src;
        if (seg < 2) {
            // A operand: x part (k<512) or rv|h part
            if (kk < INQ) {
                const __nv_bfloat16* base = (seg == 0) ? sc_xH : sc_xL;
                src = (const char*)(base + ((long long)s * BQ + row) * INQ + kk);
            } else {
                const __nv_bfloat16* base = (seg == 0) ? sc_AH : sc_AL;
                src = (const char*)(base + (long long)row * KR + (kk - INQ));
            }
        } else {
            const __nv_bfloat16* base = (seg == 2) ? sc_WfH : sc_WfL;
            src = (const char*)(base + (long long)(n0 + row) * K1 + kk);
        }
        cp16(dst, src);
    }
    cp_commit();
}

__global__ __launch_bounds__(256) void k_lstm_mma(int s) {
    extern __shared__ char dsm[];
    int tid = threadIdx.x;
    int w = tid >> 5;
    int lane = tid & 31;
    int n0 = blockIdx.x * 128;
    int z = blockIdx.z;
    int kbase = z * KSLC;
    int mBase = (w >> 2) * 64;
    int nBase = (w & 3) * 32;
    float acc[4][4][4] = {};
    lstm_stage(dsm, 0, 0, n0, kbase, s, tid);
    for (int c = 0; c < 13; c++) {
        if (c < 12) {
            lstm_stage(dsm, (c + 1) & 1, c + 1, n0, kbase, s, tid);
            cp_wait1();
        } else {
            cp_wait0();
        }
        __syncthreads();
        char* B0 = dsm + (c & 1) * L_BUFB;
        __nv_bfloat16* AHs = (__nv_bfloat16*)B0;
        __nv_bfloat16* ALs = (__nv_bfloat16*)(B0 + L_SEGB);
        __nv_bfloat16* BHs = (__nv_bfloat16*)(B0 + 2 * L_SEGB);
        __nv_bfloat16* BLs = (__nv_bfloat16*)(B0 + 3 * L_SEGB);
        #pragma unroll
        for (int kk = 0; kk < 2; kk++) {
            unsigned ah[4][4];
            unsigned al[4][4];
            int acol = kk * 16 + (lane >> 4) * 8;
            #pragma unroll
            for (int mt = 0; mt < 4; mt++) {
                int ar = mBase + mt * 16 + (lane & 15);
                ldm_x4(ah[mt], sptr(AHs + ar * L_ROWHW + acol));
                ldm_x4(al[mt], sptr(ALs + ar * L_ROWHW + acol));
            }
            int q = lane & 15;
            int bcol = kk * 16 + (q >> 3) * 8;
            #pragma unroll
            for (int nt = 0; nt < 4; nt++) {
                int br = nBase + nt * 8 + (q & 7);
                unsigned bh[2];
                unsigned bl[2];
                ldm_x2(bh, sptr(BHs + br * L_ROWHW + bcol));
                ldm_x2(bl, sptr(BLs + br * L_ROWHW + bcol));
                #pragma unroll
                for (int mt = 0; mt < 4; mt++) {
                    mma_bf16(acc[mt][nt], ah[mt], bh);
                    mma_bf16(acc[mt][nt], ah[mt], bl);
                    mma_bf16(acc[mt][nt], al[mt], bh);
                }
            }
        }
        __syncthreads();
    }
    float* dst = sc_g4 + (long long)z * BQ * G4;
    #pragma unroll
    for (int mt = 0; mt < 4; mt++) {
        int r = mBase + mt * 16 + (lane >> 2);
        #pragma unroll
        for (int nt = 0; nt < 4; nt++) {
            int cc = n0 + nBase + nt * 8 + (lane & 3) * 2;
            *(float2*)&dst[(long long)r * G4 + cc] = make_float2(acc[mt][nt][0], acc[mt][nt][1]);
            *(float2*)&dst[(long long)(r + 8) * G4 + cc] = make_float2(acc[mt][nt][2], acc[mt][nt][3]);
        }
    }
}

// ---------------- sim GEMM: K=128 fully resident (validated round 8) ----------------
__global__ __launch_bounds__(256, 1) void k_sim_mma() {
    extern __shared__ char dsm[];
    __nv_bfloat16* AHs = (__nv_bfloat16*)dsm;
    __nv_bfloat16* ALs = (__nv_bfloat16*)(dsm + 34816);
    __nv_bfloat16* BHs = (__nv_bfloat16*)(dsm + 69632);
    __nv_bfloat16* BLs = (__nv_bfloat16*)(dsm + 104448);
    int tid = threadIdx.x;
    int w = tid >> 5;
    int lane = tid & 31;
    int n0 = blockIdx.x * 128;
    int m0 = blockIdx.y * 128;
    for (int u = tid; u < 8192; u += 256) {
        int seg = u >> 11;
        int rem = u & 2047;
        int row = rem >> 4;
        int unit = rem & 15;
        unsigned dst = sptr(dsm + seg * 34816 + row * 272 + unit * 16);
        const char* src;
        if (seg == 0)      src = (const char*)sc_keysH + ((long long)(m0 + row) * WQ + unit * 8) * 2;
        else if (seg == 1) src = (const char*)sc_keysL + ((long long)(m0 + row) * WQ + unit * 8) * 2;
        else if (seg == 2) src = (const char*)sc_memnH + ((long long)(n0 + row) * WQ + unit * 8) * 2;
        else               src = (const char*)sc_memnL + ((long long)(n0 + row) * WQ + unit * 8) * 2;
        cp16(dst, src);
    }
    cp_commit();
    cp_wait0();
    __syncthreads();
    int mBase = (w >> 2) * 64;
    int nBase = (w & 3) * 32;
    float acc[4][4][4] = {};
    #pragma unroll
    for (int kk = 0; kk < 8; kk++) {
        unsigned ah[4][4];
        unsigned al[4][4];
        int acol = kk * 16 + (lane >> 4) * 8;
        #pragma unroll
        for (int mt = 0; mt < 4; mt++) {
            int ar = mBase + mt * 16 + (lane & 15);
            ldm_x4(ah[mt], sptr(AHs + ar * 136 + acol));
            ldm_x4(al[mt], sptr(ALs + ar * 136 + acol));
        }
        int q = lane & 15;
        int bcol = kk * 16 + (q >> 3) * 8;
        #pragma unroll
        for (int nt = 0; nt < 4; nt++) {
            int br = nBase + nt * 8 + (q & 7);
            unsigned bh[2];
            unsigned bl[2];
            ldm_x2(bh, sptr(BHs + br * 136 + bcol));
            ldm_x2(bl, sptr(BLs + br * 136 + bcol));
            #pragma unroll
            for (int mt = 0; mt < 4; mt++) {
                mma_bf16(acc[mt][nt], ah[mt], bh);
                mma_bf16(acc[mt][nt], ah[mt], bl);
                mma_bf16(acc[mt][nt], al[mt], bh);
            }
        }
    }
    #pragma unroll
    for (int mt = 0; mt < 4; mt++) {
        int r = m0 + mBase + mt * 16 + (lane >> 2);
        #pragma unroll
        for (int nt = 0; nt < 4; nt++) {
            int cc = n0 + nBase + nt * 8 + (lane & 3) * 2;
            *(float2*)&sc_sim[(long long)r * NQ + cc] = make_float2(acc[mt][nt][0], acc[mt][nt][1]);
            *(float2*)&sc_sim[(long long)(r + 8) * NQ + cc] = make_float2(acc[mt][nt][2], acc[mt][nt][3]);
        }
    }
}

// ---------------- remaining per-step kernels (validated) ----------------
__global__ __launch_bounds__(256) void k_gates() {
    int idx = blockIdx.x * blockDim.x + threadIdx.x;
    if (idx >= BQ * HQ) return;
    int b = idx >> 10;
    int u = idx & 1023;
    long long off = (long long)b * G4 + u * 4;
    float4 p0 = *(const float4*)&sc_g4[off];
    float4 p1 = *(const float4*)&sc_g4[(long long)BQ * G4 + off];
    float4 p2 = *(const float4*)&sc_g4[(long long)2 * BQ * G4 + off];
    float4 p3 = *(const float4*)&sc_g4[(long long)3 * BQ * G4 + off];
    float4 bg = *(const float4*)&sc_bg[u * 4];
    float i_ = p0.x + p1.x + p2.x + p3.x + bg.x;
    float f_ = p0.y + p1.y + p2.y + p3.y + bg.y;
    float g_ = p0.z + p1.z + p2.z + p3.z + bg.z;
    float o_ = p0.w + p1.w + p2.w + p3.w + bg.w;
    float c = sigmoidf_(f_) * sc_c[idx] + sigmoidf_(i_) * tanhf(g_);
    sc_c[idx] = c;
    float hv = sigmoidf_(o_) * tanhf(c);
    sc_h[idx] = hv;
    __nv_bfloat16 h;
    __nv_bfloat16 l;
    bsplit(hv, &h, &l);
    sc_AH[b * KR + WQ + u] = h;
    sc_AL[b * KR + WQ + u] = l;
}

__global__ __launch_bounds__(256) void k_headsout(float* __restrict__ out, int s) {
    __shared__ float As[32][33];
    __shared__ float Bs[32][33];
    int tid = threadIdx.x;
    int n0 = blockIdx.x * 32;
    int m0 = blockIdx.y * 32;
    int rowL = tid >> 3;
    int k4 = (tid & 7) * 4;
    int tm = tid & 7;
    int tn = tid >> 3;
    float acc[4] = {};
    for (int k0 = 0; k0 < HQ; k0 += 32) {
        float4 a = *(const float4*)(sc_h + (long long)(m0 + rowL) * HQ + k0 + k4);
        float4 b = *(const float4*)(sc_HOW + (long long)(n0 + rowL) * HQ + k0 + k4);
        As[rowL][k4 + 0] = a.x; As[rowL][k4 + 1] = a.y; As[rowL][k4 + 2] = a.z; As[rowL][k4 + 3] = a.w;
        Bs[rowL][k4 + 0] = b.x; Bs[rowL][k4 + 1] = b.y; Bs[rowL][k4 + 2] = b.z; Bs[rowL][k4 + 3] = b.w;
        __syncthreads();
        #pragma unroll
        for (int k = 0; k < 32; k++) {
            float bv = Bs[tn][k];
            #pragma unroll
            for (int i = 0; i < 4; i++) acc[i] = fmaf(As[tm * 4 + i][k], bv, acc[i]);
        }
        __syncthreads();
    }
    int n = n0 + tn;
    float bb = sc_HOb[n];
    #pragma unroll
    for (int i = 0; i < 4; i++) {
        int m = m0 + tm * 4 + i;
        float v = acc[i] + bb;
        if (n < HRP) sc_heads[m * HRP + n] = v;
        else out[((long long)m * SQ + s) * OUTQ + (n - HRP)] = v;
    }
}

__global__ __launch_bounds__(128) void k_headproc() {
    __shared__ float sh[4];
    int b = blockIdx.x;
    int w = threadIdx.x;
    const float* hd = sc_heads + b * HRP;
    float rk = hd[w];
    float wk = hd[130 + w];
    float nr2 = blockSum128(rk * rk, sh);
    float nw2 = blockSum128(wk * wk, sh);
    __nv_bfloat16 h;
    __nv_bfloat16 l;
    bsplit(rk / fmaxf(sqrtf(nr2), 1e-12f), &h, &l);
    sc_keysH[b * WQ + w] = h;
    sc_keysL[b * WQ + w] = l;
    bsplit(wk / fmaxf(sqrtf(nw2), 1e-12f), &h, &l);
    sc_keysH[(128 + b) * WQ + w] = h;
    sc_keysL[(128 + b) * WQ + w] = l;
    if (w == 0) {
        sc_beta[b] = softplusf_(hd[128]);
        sc_gamma[b] = 1.0f + softplusf_(hd[129]);
        sc_beta[128 + b] = softplusf_(hd[258]);
        sc_gamma[128 + b] = 1.0f + softplusf_(hd[259]);
    }
    sc_er[b * WQ + w] = sigmoidf_(hd[260 + w]);
    sc_ad[b * WQ + w] = tanhf(hd[388 + w]);
}

__global__ __launch_bounds__(512) void k_softmax512() {
    __shared__ float sh[16];
    __shared__ float bcv;
    int q = blockIdx.x;
    int tid = threadIdx.x;
    int lane = tid & 31;
    int wid = tid >> 5;
    float beta = sc_beta[q];
    float gamma = sc_gamma[q];
    const float* row = sc_sim + (long long)q * NQ;
    float v[32];
    float mx = -1e30f;
    #pragma unroll
    for (int i = 0; i < 32; i++) { v[i] = row[tid + i * 512]; mx = fmaxf(mx, v[i]); }
    #pragma unroll
    for (int o = 16; o; o >>= 1) mx = fmaxf(mx, __shfl_xor_sync(0xffffffffu, mx, o));
    if (lane == 0) sh[wid] = mx;
    __syncthreads();
    if (tid == 0) {
        float m = sh[0];
        #pragma unroll
        for (int i = 1; i < 16; i++) m = fmaxf(m, sh[i]);
        bcv = m;
    }
    __syncthreads();
    mx = bcv;
    float s = 0.f;
    #pragma unroll
    for (int i = 0; i < 32; i++) { v[i] = __expf(beta * (v[i] - mx)); s += v[i]; }
    __syncthreads();
    #pragma unroll
    for (int o = 16; o; o >>= 1) s += __shfl_xor_sync(0xffffffffu, s, o);
    if (lane == 0) sh[wid] = s;
    __syncthreads();
    if (tid == 0) {
        float t = 0.f;
        #pragma unroll
        for (int i = 0; i < 16; i++) t += sh[i];
        bcv = 1.0f / t;
    }
    __syncthreads();
    float inv = bcv;
    if (q < 128) {
        float* rw = sc_rw + (long long)q * NQ;
        #pragma unroll
        for (int i = 0; i < 32; i++) {
            int n = tid + i * 512;
            rw[n] = gamma * (v[i] * inv) + (1.0f - gamma) * rw[n];
        }
    } else {
        float* ww = sc_ww + (long long)(q - 128) * NQ;
        float u = (1.0f - gamma) * (1.0f / (float)NQ);
        #pragma unroll
        for (int i = 0; i < 32; i++) {
            ww[tid + i * 512] = gamma * (v[i] * inv) + u;
        }
    }
}

__global__ __launch_bounds__(256) void k_memupd_rv() {
    __shared__ __align__(16) float mns[64][132];
    __shared__ __align__(16) float ubuf[2656];
    __shared__ float rowsq[64][4];
    __shared__ float sInv[64];
    float (*sw)[68] = (float(*)[68])ubuf;
    float (*se)[132] = (float(*)[132])(ubuf + 8 * 68);
    float (*sa)[132] = (float(*)[132])(ubuf + 8 * 68 + 8 * 132);
    float (*srw)[132] = (float(*)[132])ubuf;
    int tid = threadIdx.x;
    int n0 = blockIdx.x * 64;
    int txn = tid & 15;
    int txw = tid >> 4;
    float ae[4][8] = {};
    float aa[4][8] = {};
    for (int b0 = 0; b0 < BQ; b0 += 8) {
        int kk = tid >> 5;
        int half = tid & 31;
        *(float2*)&sw[kk][half * 2] = *(const float2*)&sc_ww[(long long)(b0 + kk) * NQ + n0 + half * 2];
        *(float4*)&se[kk][half * 4] = *(const float4*)&sc_er[(b0 + kk) * WQ + half * 4];
        *(float4*)&sa[kk][half * 4] = *(const float4*)&sc_ad[(b0 + kk) * WQ + half * 4];
        __syncthreads();
        #pragma unroll
        for (int k = 0; k < 8; k++) {
            float4 w4 = *(const float4*)&sw[k][txn * 4];
            float4 e0 = *(const float4*)&se[k][txw * 8];
            float4 e1 = *(const float4*)&se[k][txw * 8 + 4];
            float4 a0 = *(const float4*)&sa[k][txw * 8];
            float4 a1 = *(const float4*)&sa[k][txw * 8 + 4];
            float wv[4] = {w4.x, w4.y, w4.z, w4.w};
            float ev[8] = {e0.x, e0.y, e0.z, e0.w, e1.x, e1.y, e1.z, e1.w};
            float av[8] = {a0.x, a0.y, a0.z, a0.w, a1.x, a1.y, a1.z, a1.w};
            #pragma unroll
            for (int i = 0; i < 4; i++) {
                #pragma unroll
                for (int j = 0; j < 8; j++) {
                    ae[i][j] = fmaf(wv[i], ev[j], ae[i][j]);
                    aa[i][j] = fmaf(wv[i], av[j], aa[i][j]);
                }
            }
        }
        __syncthreads();
    }
    #pragma unroll
    for (int i = 0; i < 4; i++) {
        int nl = txn * 4 + i;
        long long base = (long long)(n0 + nl) * WQ + txw * 8;
        float4 m0v = *(const float4*)&sc_mem[base];
        float4 m1v = *(const float4*)&sc_mem[base + 4];
        float r[8] = {m0v.x, m0v.y, m0v.z, m0v.w, m1v.x, m1v.y, m1v.z, m1v.w};
        #pragma unroll
        for (int j = 0; j < 8; j++) r[j] = r[j] * (1.0f - ae[i][j]) + aa[i][j];
        *(float4*)&sc_mem[base] = make_float4(r[0], r[1], r[2], r[3]);
        *(float4*)&sc_mem[base + 4] = make_float4(r[4], r[5], r[6], r[7]);
        *(float4*)&mns[nl][txw * 8] = make_float4(r[0], r[1], r[2], r[3]);
        *(float4*)&mns[nl][txw * 8 + 4] = make_float4(r[4], r[5], r[6], r[7]);
    }
    __syncthreads();
    {
        int r = tid >> 2;
        int qq = tid & 3;
        float s = 0.f;
        #pragma unroll
        for (int t = 0; t < 32; t += 4) {
            float4 v = *(const float4*)&mns[r][qq * 32 + t];
            s += v.x * v.x + v.y * v.y + v.z * v.z + v.w * v.w;
        }
        rowsq[r][qq] = s;
    }
    __syncthreads();
    if (tid < 64) {
        float s = rowsq[tid][0] + rowsq[tid][1] + rowsq[tid][2] + rowsq[tid][3];
        sInv[tid] = 1.0f / fmaxf(sqrtf(s), 1e-12f);
    }
    __syncthreads();
    for (int i = tid; i < 64 * 32; i += 256) {
        int r = i >> 5;
        int c = (i & 31) * 4;
        float inv = sInv[r];
        float4 v = *(const float4*)&mns[r][c];
        __nv_bfloat16 h0, l0, h1, l1, h2, l2, h3, l3;
        bsplit(v.x * inv, &h0, &l0);
        bsplit(v.y * inv, &h1, &l1);
        bsplit(v.z * inv, &h2, &l2);
        bsplit(v.w * inv, &h3, &l3);
        long long o = (long long)(n0 + r) * WQ + c;
        st_bf2(&sc_memnH[o], h0, h1);
        st_bf2(&sc_memnH[o + 2], h2, h3);
        st_bf2(&sc_memnL[o], l0, l1);
        st_bf2(&sc_memnL[o + 2], l2, l3);
    }
    int tb = tid & 15;
    int tw = tid >> 4;
    float racc[8][8] = {};
    for (int nc = 0; nc < 4; nc++) {
        __syncthreads();
        #pragma unroll
        for (int r = 0; r < 8; r++) {
            int b = tw + r * 16;
            srw[tb][b] = sc_rw[(long long)b * NQ + n0 + nc * 16 + tb];
        }
        __syncthreads();
        #pragma unroll
        for (int nn = 0; nn < 16; nn++) {
            float4 r0 = *(const float4*)&srw[nn][tb * 8];
            float4 r1 = *(const float4*)&srw[nn][tb * 8 + 4];
            int nl = nc * 16 + nn;
            float4 q0 = *(const float4*)&mns[nl][tw * 8];
            float4 q1 = *(const float4*)&mns[nl][tw * 8 + 4];
            float rb[8] = {r0.x, r0.y, r0.z, r0.w, r1.x, r1.y, r1.z, r1.w};
            float mw[8] = {q0.x, q0.y, q0.z, q0.w, q1.x, q1.y, q1.z, q1.w};
            #pragma unroll
            for (int i = 0; i < 8; i++) {
                #pragma unroll
                for (int j = 0; j < 8; j++) racc[i][j] = fmaf(rb[i], mw[j], racc[i][j]);
            }
        }
    }
    float* dst = sc_rvpart + (long long)blockIdx.x * BQ * WQ;
    #pragma unroll
    for (int i = 0; i < 8; i++) {
        int b = tb * 8 + i;
        *(float4*)&dst[b * WQ + tw * 8] = make_float4(racc[i][0], racc[i][1], racc[i][2], racc[i][3]);
        *(float4*)&dst[b * WQ + tw * 8 + 4] = make_float4(racc[i][4], racc[i][5], racc[i][6], racc[i][7]);
    }
}

__global__ __launch_bounds__(256) void k_rvreduce() {
    __shared__ float4 red[32][8];
    int tid = threadIdx.x;
    int outIdx = blockIdx.x * 32 + (tid >> 3);
    int sub = tid & 7;
    const float4* p = (const float4*)sc_rvpart;
    float4 s = make_float4(0.f, 0.f, 0.f, 0.f);
    #pragma unroll 4
    for (int i = 0; i < 32; i++) {
        float4 t = p[(long long)(sub + i * 8) * 4096 + outIdx];
        s.x += t.x; s.y += t.y; s.z += t.z; s.w += t.w;
    }
    red[tid >> 3][sub] = s;
    __syncthreads();
    if (sub == 0) {
        float4 a = make_float4(0.f, 0.f, 0.f, 0.f);
        #pragma unroll
        for (int i = 0; i < 8; i++) {
            float4 t = red[tid >> 3][i];
            a.x += t.x; a.y += t.y; a.z += t.z; a.w += t.w;
        }
        int b = outIdx >> 5;
        int c0 = (outIdx & 31) * 4;
        __nv_bfloat16 h0, l0, h1, l1, h2, l2, h3, l3;
        bsplit(a.x, &h0, &l0);
        bsplit(a.y, &h1, &l1);
        bsplit(a.z, &h2, &l2);
        bsplit(a.w, &h3, &l3);
        int o = b * KR + c0;
        st_bf2(&sc_AH[o], h0, h1);
        st_bf2(&sc_AH[o + 2], h2, h3);
        st_bf2(&sc_AL[o], l0, l1);
        st_bf2(&sc_AL[o + 2], l2, l3);
    }
}

// ---------------- host launcher ----------------
extern "C" void kernel_launch(void* const* d_in, const int* in_sizes, int n_in,
                              void* d_out, int out_size) {
    const float* x = (const float*)d_in[0];
    const float* memory = (const float*)d_in[1];
    const float* Wih = (const float*)d_in[2];
    const float* Whh = (const float*)d_in[3];
    const float* bih = (const float*)d_in[4];
    const float* bhh = (const float*)d_in[5];
    const float* Wout = (const float*)d_in[6];
    const float* bout = (const float*)d_in[7];
    const float* rkW = (const float*)d_in[8];
    const float* rkb = (const float*)d_in[9];
    const float* rbW = (const float*)d_in[10];
    const float* rbb = (const float*)d_in[11];
    const float* rgW = (const float*)d_in[12];
    const float* rgb = (const float*)d_in[13];
    const float* wkW = (const float*)d_in[14];
    const float* wkb = (const float*)d_in[15];
    const float* wbW = (const float*)d_in[16];
    const float* wbb = (const float*)d_in[17];
    const float* wgW = (const float*)d_in[18];
    const float* wgb = (const float*)d_in[19];
    const float* erW = (const float*)d_in[20];
    const float* erb = (const float*)d_in[21];
    const float* adW = (const float*)d_in[22];
    const float* adb = (const float*)d_in[23];
    const float* pW = (const float*)d_in[24];
    const float* pb = (const float*)d_in[25];
    float* out = (float*)d_out;

    cudaFuncSetAttribute(k_lstm_mma, cudaFuncAttributeMaxDynamicSharedMemorySize, 2 * L_BUFB);
    cudaFuncSetAttribute(k_sim_mma, cudaFuncAttributeMaxDynamicSharedMemorySize, 139264);

    // prologue: exactly 5 launches
    long long setup_total = (long long)G4 * K1 + G4 + (long long)CP * HQ + (long long)HRP * CP;
    k_setup_w<<<(int)((setup_total + 255) / 256), 256>>>(Wih, Whh, bih, bhh, Wout,
                                                         rkW, rbW, rgW, wkW, wbW, wgW, erW, adW);
    k_setup_x<<<(int)(((long long)SQ * BQ * INQ + 255) / 256), 256>>>(x);
    k_initmem<<<2048 + 9792, 256>>>(memory);
    k_biases<<<HOW, 128>>>(bout, pW, pb, rkW, rbW, rgW, wkW, wbW, wgW, erW, adW,
                           rkb, rbb, rgb, wkb, wbb, wgb, erb, adb);
    k_fold<<<dim3(HQ / 32, 34), 256>>>(pW, Wout);

    for (int s = 0; s < SQ; s++) {
        k_lstm_mma<<<dim3(G4 / 128, 1, NZ), 256, 2 * L_BUFB>>>(s);
        k_gates<<<(BQ * HQ + 255) / 256, 256>>>();
        k_headsout<<<dim3(HOW / 32, BQ / 32), 256>>>(out, s);
        k_headproc<<<BQ, 128>>>();
        k_sim_mma<<<dim3(NQ / 128, 2), 256, 139264>>>();
        k_softmax512<<<2 * BQ, 512>>>();
        k_memupd_rv<<<NQ / 64, 256>>>();
        k_rvreduce<<<128, 256>>>();
    }
}

// round 10
// speedup vs baseline: 1.5173x; 1.0691x over previous
#include <cuda_runtime.h>
#include <cuda_bf16.h>
#include <math.h>

#define BQ   128
#define SQ   32
#define INQ  512
#define HQ   1024
#define OUTQ 512
#define NQ   16384
#define WQ   128
#define CQ   899
#define CP   960
#define K1   1664
#define KR   1152
#define G4   4096
#define HRP  576
#define HOW  1088
#define NCHUNK 128
#define NZ   4
#define KSLC 416

// ---------------- device globals ----------------
__device__ float sc_mem[NQ * WQ];
__device__ __nv_bfloat16 sc_WfH[(long long)G4 * K1];
__device__ __nv_bfloat16 sc_WfL[(long long)G4 * K1];
__device__ __nv_bfloat16 sc_xH[(long long)SQ * BQ * INQ];
__device__ __nv_bfloat16 sc_xL[(long long)SQ * BQ * INQ];
__device__ float sc_bg[G4];
__device__ float sc_WoutP[CP * HQ];
__device__ float sc_HW[HRP * CP];
__device__ float sc_HOW[HOW * HQ];
__device__ float sc_HOb[HOW];
__device__ float sc_g4[NZ * BQ * G4];
__device__ float sc_h[BQ * HQ];
__device__ float sc_c[BQ * HQ];
__device__ __nv_bfloat16 sc_AH[BQ * KR];
__device__ __nv_bfloat16 sc_AL[BQ * KR];
__device__ float sc_rw[BQ * NQ];
__device__ __nv_bfloat16 sc_rwH[(long long)BQ * NQ];
__device__ __nv_bfloat16 sc_rwL[(long long)BQ * NQ];
__device__ __nv_bfloat16 sc_wwH[(long long)BQ * NQ];
__device__ __nv_bfloat16 sc_wwL[(long long)BQ * NQ];
__device__ float sc_heads[BQ * HRP];
__device__ __nv_bfloat16 sc_keysH[2 * BQ * WQ];
__device__ __nv_bfloat16 sc_keysL[2 * BQ * WQ];
__device__ __nv_bfloat16 sc_memnH[NQ * WQ];
__device__ __nv_bfloat16 sc_memnL[NQ * WQ];
__device__ __nv_bfloat16 sc_erH[BQ * WQ];
__device__ __nv_bfloat16 sc_erL[BQ * WQ];
__device__ __nv_bfloat16 sc_adH[BQ * WQ];
__device__ __nv_bfloat16 sc_adL[BQ * WQ];
__device__ float sc_beta[2 * BQ];
__device__ float sc_gamma[2 * BQ];
__device__ float sc_sim[2 * BQ * NQ];
__device__ float sc_rvpart[NCHUNK * BQ * WQ];

// ---------------- helpers ----------------
__device__ __forceinline__ float sigmoidf_(float x) { return 1.0f / (1.0f + expf(-x)); }
__device__ __forceinline__ float softplusf_(float x) { return x > 20.0f ? x : log1pf(expf(x)); }

__device__ __forceinline__ void bsplit(float v, __nv_bfloat16* h, __nv_bfloat16* l) {
    __nv_bfloat16 hi = __float2bfloat16(v);
    *h = hi;
    *l = __float2bfloat16(v - __bfloat162float(hi));
}

__device__ __forceinline__ void st_bf2(__nv_bfloat16* p, __nv_bfloat16 a, __nv_bfloat16 b) {
    __nv_bfloat162 t;
    t.x = a;
    t.y = b;
    *(__nv_bfloat162*)p = t;
}

__device__ __forceinline__ unsigned sptr(const void* p) {
    return (unsigned)__cvta_generic_to_shared(p);
}

__device__ __forceinline__ void ldm_x4(unsigned* r, unsigned a) {
    asm volatile("ldmatrix.sync.aligned.m8n8.x4.shared.b16 {%0,%1,%2,%3}, [%4];"
        : "=r"(r[0]), "=r"(r[1]), "=r"(r[2]), "=r"(r[3]) : "r"(a));
}

__device__ __forceinline__ void ldm_x2(unsigned* r, unsigned a) {
    asm volatile("ldmatrix.sync.aligned.m8n8.x2.shared.b16 {%0,%1}, [%2];"
        : "=r"(r[0]), "=r"(r[1]) : "r"(a));
}

__device__ __forceinline__ void ldm_x4t(unsigned* r, unsigned a) {
    asm volatile("ldmatrix.sync.aligned.m8n8.x4.trans.shared.b16 {%0,%1,%2,%3}, [%4];"
        : "=r"(r[0]), "=r"(r[1]), "=r"(r[2]), "=r"(r[3]) : "r"(a));
}

__device__ __forceinline__ void ldm_x2t(unsigned* r, unsigned a) {
    asm volatile("ldmatrix.sync.aligned.m8n8.x2.trans.shared.b16 {%0,%1}, [%2];"
        : "=r"(r[0]), "=r"(r[1]) : "r"(a));
}

__device__ __forceinline__ void mma_bf16(float* d, const unsigned* a, const unsigned* b) {
    asm volatile("mma.sync.aligned.m16n8k16.row.col.f32.bf16.bf16.f32 "
        "{%0,%1,%2,%3}, {%4,%5,%6,%7}, {%8,%9}, {%0,%1,%2,%3};"
        : "+f"(d[0]), "+f"(d[1]), "+f"(d[2]), "+f"(d[3])
        : "r"(a[0]), "r"(a[1]), "r"(a[2]), "r"(a[3]), "r"(b[0]), "r"(b[1]));
}

__device__ __forceinline__ void cp16(unsigned dst, const void* src) {
    asm volatile("cp.async.cg.shared.global [%0], [%1], 16;" :: "r"(dst), "l"(src));
}
__device__ __forceinline__ void cp_commit() { asm volatile("cp.async.commit_group;"); }
__device__ __forceinline__ void cp_wait0() { asm volatile("cp.async.wait_group 0;"); }
__device__ __forceinline__ void cp_wait1() { asm volatile("cp.async.wait_group 1;"); }

__device__ __forceinline__ float blockSum128(float v, float* sh) {
    #pragma unroll
    for (int o = 16; o; o >>= 1) v += __shfl_xor_sync(0xffffffffu, v, o);
    if ((threadIdx.x & 31) == 0) sh[threadIdx.x >> 5] = v;
    __syncthreads();
    float r = sh[0] + sh[1] + sh[2] + sh[3];
    __syncthreads();
    return r;
}

__device__ __forceinline__ float hw_elem(int r, int k,
    const float* rkW, const float* rbW, const float* rgW,
    const float* wkW, const float* wbW, const float* wgW,
    const float* erW, const float* adW) {
    if (k >= CQ || r >= 516) return 0.0f;
    if (r < 128) return rkW[r * CQ + k];
    if (r == 128) return rbW[k];
    if (r == 129) return rgW[k];
    if (r < 258) return wkW[(r - 130) * CQ + k];
    if (r == 258) return wbW[k];
    if (r == 259) return wgW[k];
    if (r < 388) return erW[(r - 260) * CQ + k];
    return adW[(r - 388) * CQ + k];
}

__device__ __forceinline__ float hb_elem(int r,
    const float* rkb, const float* rbb, const float* rgb,
    const float* wkb, const float* wbb, const float* wgb,
    const float* erb, const float* adb) {
    if (r < 128) return rkb[r];
    if (r == 128) return rbb[0];
    if (r == 129) return rgb[0];
    if (r < 258) return wkb[r - 130];
    if (r == 258) return wbb[0];
    if (r == 259) return wgb[0];
    if (r < 388) return erb[r - 260];
    if (r < 516) return adb[r - 388];
    return 0.0f;
}

// ---------------- prologue ----------------
__global__ void k_setup_w(const float* __restrict__ Wih, const float* __restrict__ Whh,
                          const float* __restrict__ bih, const float* __restrict__ bhh,
                          const float* __restrict__ Wout,
                          const float* rkW, const float* rbW, const float* rgW,
                          const float* wkW, const float* wbW, const float* wgW,
                          const float* erW, const float* adW) {
    long long i = (long long)blockIdx.x * blockDim.x + threadIdx.x;
    const long long NW = (long long)G4 * K1;
    const long long ND = (long long)CP * HQ;
    const long long NE = (long long)HRP * CP;
    if (i < NW) {
        int r = (int)(i / K1);
        int k = (int)(i % K1);
        int src = (r & 3) * HQ + (r >> 2);
        float v = (k < INQ + WQ) ? Wih[src * (INQ + WQ) + k] : Whh[src * HQ + (k - INQ - WQ)];
        __nv_bfloat16 h, l;
        bsplit(v, &h, &l);
        sc_WfH[i] = h;
        sc_WfL[i] = l;
        return;
    }
    i -= NW;
    if (i < G4) {
        int r = (int)i;
        int src = (r & 3) * HQ + (r >> 2);
        sc_bg[r] = bih[src] + bhh[src];
        return;
    }
    i -= G4;
    if (i < ND) {
        int r = (int)(i / HQ);
        sc_WoutP[i] = (r < CQ) ? Wout[(long long)r * HQ + (i % HQ)] : 0.0f;
        return;
    }
    i -= ND;
    if (i < NE) {
        int r = (int)(i / CP);
        int k = (int)(i % CP);
        sc_HW[i] = hw_elem(r, k, rkW, rbW, rgW, wkW, wbW, wgW, erW, adW);
        return;
    }
}

__global__ void k_setup_x(const float* __restrict__ x) {
    long long i = (long long)blockIdx.x * blockDim.x + threadIdx.x;
    if (i >= (long long)SQ * BQ * INQ) return;
    int k = (int)(i % INQ);
    long long sb = i / INQ;
    int b = (int)(sb % BQ);
    int s = (int)(sb / BQ);
    float v = x[((long long)b * SQ + s) * INQ + k];
    __nv_bfloat16 h, l;
    bsplit(v, &h, &l);
    sc_xH[i] = h;
    sc_xL[i] = l;
}

__global__ __launch_bounds__(256) void k_initmem(const float* __restrict__ memory) {
    if (blockIdx.x < 2048) {
        int row = blockIdx.x * 8 + (threadIdx.x >> 5);
        int lane = threadIdx.x & 31;
        const float* src = memory + (long long)row * WQ;
        float v[4];
        float s = 0.f;
        #pragma unroll
        for (int i = 0; i < 4; i++) { v[i] = src[lane + 32 * i]; s += v[i] * v[i]; }
        #pragma unroll
        for (int o = 16; o; o >>= 1) s += __shfl_xor_sync(0xffffffffu, s, o);
        float inv = 1.0f / fmaxf(sqrtf(s), 1e-12f);
        #pragma unroll
        for (int i = 0; i < 4; i++) {
            long long o = (long long)row * WQ + lane + 32 * i;
            sc_mem[o] = v[i];
            __nv_bfloat16 h, l;
            bsplit(v[i] * inv, &h, &l);
            sc_memnH[o] = h;
            sc_memnL[o] = l;
        }
    } else {
        long long base = (long long)(blockIdx.x - 2048) * 256 + threadIdx.x;
        if (base < (long long)BQ * NQ) { sc_rw[base] = 1.0f / (float)NQ; return; }
        base -= (long long)BQ * NQ;
        if (base < (long long)BQ * NQ / 2) { ((unsigned*)sc_rwH)[base] = 0x38803880u; return; }
        base -= (long long)BQ * NQ / 2;
        if (base < (long long)BQ * NQ / 2) { ((unsigned*)sc_rwL)[base] = 0u; return; }
        base -= (long long)BQ * NQ / 2;
        if (base < BQ * HQ) { sc_h[base] = 0.0f; return; }
        base -= BQ * HQ;
        if (base < BQ * HQ) { sc_c[base] = 0.0f; return; }
        base -= BQ * HQ;
        if (base < BQ * KR / 2) { ((unsigned*)sc_AH)[base] = 0u; return; }
        base -= BQ * KR / 2;
        if (base < BQ * KR / 2) { ((unsigned*)sc_AL)[base] = 0u; return; }
    }
}

__global__ __launch_bounds__(128) void k_biases(const float* bout, const float* pW, const float* pb,
    const float* rkW, const float* rbW, const float* rgW,
    const float* wkW, const float* wbW, const float* wgW,
    const float* erW, const float* adW,
    const float* rkb, const float* rbb, const float* rgb,
    const float* wkb, const float* wbb, const float* wgb,
    const float* erb, const float* adb) {
    __shared__ float sh[4];
    int r = blockIdx.x;
    int t = threadIdx.x;
    float s = 0.f;
    if (r < HRP) {
        for (int c = t; c < CQ; c += 128)
            s += hw_elem(r, c, rkW, rbW, rgW, wkW, wbW, wgW, erW, adW) * bout[c];
        s = blockSum128(s, sh);
        if (t == 0) sc_HOb[r] = s + hb_elem(r, rkb, rbb, rgb, wkb, wbb, wgb, erb, adb);
    } else {
        int o = r - HRP;
        for (int c = t; c < OUTQ; c += 128) s += pW[o * OUTQ + c] * bout[c];
        s = blockSum128(s, sh);
        if (t == 0) sc_HOb[r] = s + pb[o];
    }
}

__global__ __launch_bounds__(256) void k_fold(const float* __restrict__ pW,
                                              const float* __restrict__ Wout) {
    __shared__ float As[32][36];
    __shared__ float Bs[32][36];
    int tid = threadIdx.x;
    int n0 = blockIdx.x * 32;
    int second = (blockIdx.y >= 18) ? 1 : 0;
    int m0 = second ? (blockIdx.y - 18) * 32 : blockIdx.y * 32;
    const float* A = second ? pW : sc_HW;
    const float* B = second ? Wout : sc_WoutP;
    int lda = second ? OUTQ : CP;
    int K = second ? OUTQ : CP;
    int dstRow = second ? HRP : 0;
    int rowL = tid >> 3;
    int k4 = (tid & 7) * 4;
    int tm = tid & 7;
    int tn = tid >> 3;
    float acc[4] = {};
    for (int k0 = 0; k0 < K; k0 += 32) {
        float4 a = *(const float4*)(A + (long long)(m0 + rowL) * lda + k0 + k4);
        float4 b = *(const float4*)(B + (long long)(k0 + rowL) * HQ + n0 + k4);
        As[rowL][k4 + 0] = a.x; As[rowL][k4 + 1] = a.y; As[rowL][k4 + 2] = a.z; As[rowL][k4 + 3] = a.w;
        Bs[rowL][k4 + 0] = b.x; Bs[rowL][k4 + 1] = b.y; Bs[rowL][k4 + 2] = b.z; Bs[rowL][k4 + 3] = b.w;
        __syncthreads();
        #pragma unroll
        for (int k = 0; k < 32; k++) {
            float bv = Bs[k][tn];
            #pragma unroll
            for (int i = 0; i < 4; i++) acc[i] = fmaf(As[tm * 4 + i][k], bv, acc[i]);
        }
        __syncthreads();
    }
    #pragma unroll
    for (int i = 0; i < 4; i++)
        sc_HOW[(long long)(dstRow + m0 + tm * 4 + i) * HQ + n0 + tn] = acc[i];
}

// ---------------- LSTM full GEMM (validated round 9) ----------------
#define L_ROWHW 40
#define L_SEGB  (128 * L_ROWHW * 2)
#define L_BUFB  (4 * L_SEGB)

__device__ __forceinline__ void lstm_stage(char* dsm, int buf, int c, int n0, int kbase, int s, int tid) {
    for (int u = tid; u < 2048; u += 256) {
        int seg = u >> 9;
        int rem = u & 511;
        int row = rem >> 2;
        int unit = rem & 3;
        unsigned dst = sptr(dsm + buf * L_BUFB + seg * L_SEGB + row * (L_ROWHW * 2) + unit * 16);
        int kk = kbase + c * 32 + unit * 8;
        const char* src;
        if (seg < 2) {
            if (kk < INQ) {
                const __nv_bfloat16* base = (seg == 0) ? sc_xH : sc_xL;
                src = (const char*)(base + ((long long)s * BQ + row) * INQ + kk);
            } else {
                const __nv_bfloat16* base = (seg == 0) ? sc_AH : sc_AL;
                src = (const char*)(base + (long long)row * KR + (kk - INQ));
            }
        } else {
            const __nv_bfloat16* base = (seg == 2) ? sc_WfH : sc_WfL;
            src = (const char*)(base + (long long)(n0 + row) * K1 + kk);
        }
        cp16(dst, src);
    }
    cp_commit();
}

__global__ __launch_bounds__(256) void k_lstm_mma(int s) {
    extern __shared__ char dsm[];
    int tid = threadIdx.x;
    int w = tid >> 5;
    int lane = tid & 31;
    int n0 = blockIdx.x * 128;
    int z = blockIdx.z;
    int kbase = z * KSLC;
    int mBase = (w >> 2) * 64;
    int nBase = (w & 3) * 32;
    float acc[4][4][4] = {};
    lstm_stage(dsm, 0, 0, n0, kbase, s, tid);
    for (int c = 0; c < 13; c++) {
        if (c < 12) {
            lstm_stage(dsm, (c + 1) & 1, c + 1, n0, kbase, s, tid);
            cp_wait1();
        } else {
            cp_wait0();
        }
        __syncthreads();
        char* B0 = dsm + (c & 1) * L_BUFB;
        __nv_bfloat16* AHs = (__nv_bfloat16*)B0;
        __nv_bfloat16* ALs = (__nv_bfloat16*)(B0 + L_SEGB);
        __nv_bfloat16* BHs = (__nv_bfloat16*)(B0 + 2 * L_SEGB);
        __nv_bfloat16* BLs = (__nv_bfloat16*)(B0 + 3 * L_SEGB);
        #pragma unroll
        for (int kk = 0; kk < 2; kk++) {
            unsigned ah[4][4];
            unsigned al[4][4];
            int acol = kk * 16 + (lane >> 4) * 8;
            #pragma unroll
            for (int mt = 0; mt < 4; mt++) {
                int ar = mBase + mt * 16 + (lane & 15);
                ldm_x4(ah[mt], sptr(AHs + ar * L_ROWHW + acol));
                ldm_x4(al[mt], sptr(ALs + ar * L_ROWHW + acol));
            }
            int q = lane & 15;
            int bcol = kk * 16 + (q >> 3) * 8;
            #pragma unroll
            for (int nt = 0; nt < 4; nt++) {
                int br = nBase + nt * 8 + (q & 7);
                unsigned bh[2];
                unsigned bl[2];
                ldm_x2(bh, sptr(BHs + br * L_ROWHW + bcol));
                ldm_x2(bl, sptr(BLs + br * L_ROWHW + bcol));
                #pragma unroll
                for (int mt = 0; mt < 4; mt++) {
                    mma_bf16(acc[mt][nt], ah[mt], bh);
                    mma_bf16(acc[mt][nt], ah[mt], bl);
                    mma_bf16(acc[mt][nt], al[mt], bh);
                }
            }
        }
        __syncthreads();
    }
    float* dst = sc_g4 + (long long)z * BQ * G4;
    #pragma unroll
    for (int mt = 0; mt < 4; mt++) {
        int r = mBase + mt * 16 + (lane >> 2);
        #pragma unroll
        for (int nt = 0; nt < 4; nt++) {
            int cc = n0 + nBase + nt * 8 + (lane & 3) * 2;
            *(float2*)&dst[(long long)r * G4 + cc] = make_float2(acc[mt][nt][0], acc[mt][nt][1]);
            *(float2*)&dst[(long long)(r + 8) * G4 + cc] = make_float2(acc[mt][nt][2], acc[mt][nt][3]);
        }
    }
}

// ---------------- sim GEMM (validated round 8) ----------------
__global__ __launch_bounds__(256, 1) void k_sim_mma() {
    extern __shared__ char dsm[];
    __nv_bfloat16* AHs = (__nv_bfloat16*)dsm;
    __nv_bfloat16* ALs = (__nv_bfloat16*)(dsm + 34816);
    __nv_bfloat16* BHs = (__nv_bfloat16*)(dsm + 69632);
    __nv_bfloat16* BLs = (__nv_bfloat16*)(dsm + 104448);
    int tid = threadIdx.x;
    int w = tid >> 5;
    int lane = tid & 31;
    int n0 = blockIdx.x * 128;
    int m0 = blockIdx.y * 128;
    for (int u = tid; u < 8192; u += 256) {
        int seg = u >> 11;
        int rem = u & 2047;
        int row = rem >> 4;
        int unit = rem & 15;
        unsigned dst = sptr(dsm + seg * 34816 + row * 272 + unit * 16);
        const char* src;
        if (seg == 0)      src = (const char*)sc_keysH + ((long long)(m0 + row) * WQ + unit * 8) * 2;
        else if (seg == 1) src = (const char*)sc_keysL + ((long long)(m0 + row) * WQ + unit * 8) * 2;
        else if (seg == 2) src = (const char*)sc_memnH + ((long long)(n0 + row) * WQ + unit * 8) * 2;
        else               src = (const char*)sc_memnL + ((long long)(n0 + row) * WQ + unit * 8) * 2;
        cp16(dst, src);
    }
    cp_commit();
    cp_wait0();
    __syncthreads();
    int mBase = (w >> 2) * 64;
    int nBase = (w & 3) * 32;
    float acc[4][4][4] = {};
    #pragma unroll
    for (int kk = 0; kk < 8; kk++) {
        unsigned ah[4][4];
        unsigned al[4][4];
        int acol = kk * 16 + (lane >> 4) * 8;
        #pragma unroll
        for (int mt = 0; mt < 4; mt++) {
            int ar = mBase + mt * 16 + (lane & 15);
            ldm_x4(ah[mt], sptr(AHs + ar * 136 + acol));
            ldm_x4(al[mt], sptr(ALs + ar * 136 + acol));
        }
        int q = lane & 15;
        int bcol = kk * 16 + (q >> 3) * 8;
        #pragma unroll
        for (int nt = 0; nt < 4; nt++) {
            int br = nBase + nt * 8 + (q & 7);
            unsigned bh[2];
            unsigned bl[2];
            ldm_x2(bh, sptr(BHs + br * 136 + bcol));
            ldm_x2(bl, sptr(BLs + br * 136 + bcol));
            #pragma unroll
            for (int mt = 0; mt < 4; mt++) {
                mma_bf16(acc[mt][nt], ah[mt], bh);
                mma_bf16(acc[mt][nt], ah[mt], bl);
                mma_bf16(acc[mt][nt], al[mt], bh);
            }
        }
    }
    #pragma unroll
    for (int mt = 0; mt < 4; mt++) {
        int r = m0 + mBase + mt * 16 + (lane >> 2);
        #pragma unroll
        for (int nt = 0; nt < 4; nt++) {
            int cc = n0 + nBase + nt * 8 + (lane & 3) * 2;
            *(float2*)&sc_sim[(long long)r * NQ + cc] = make_float2(acc[mt][nt][0], acc[mt][nt][1]);
            *(float2*)&sc_sim[(long long)(r + 8) * NQ + cc] = make_float2(acc[mt][nt][2], acc[mt][nt][3]);
        }
    }
}

// ---------------- per-step small kernels ----------------
__global__ __launch_bounds__(256) void k_gates() {
    int idx = blockIdx.x * blockDim.x + threadIdx.x;
    if (idx >= BQ * HQ) return;
    int b = idx >> 10;
    int u = idx & 1023;
    long long off = (long long)b * G4 + u * 4;
    float4 p0 = *(const float4*)&sc_g4[off];
    float4 p1 = *(const float4*)&sc_g4[(long long)BQ * G4 + off];
    float4 p2 = *(const float4*)&sc_g4[(long long)2 * BQ * G4 + off];
    float4 p3 = *(const float4*)&sc_g4[(long long)3 * BQ * G4 + off];
    float4 bg = *(const float4*)&sc_bg[u * 4];
    float i_ = p0.x + p1.x + p2.x + p3.x + bg.x;
    float f_ = p0.y + p1.y + p2.y + p3.y + bg.y;
    float g_ = p0.z + p1.z + p2.z + p3.z + bg.z;
    float o_ = p0.w + p1.w + p2.w + p3.w + bg.w;
    float c = sigmoidf_(f_) * sc_c[idx] + sigmoidf_(i_) * tanhf(g_);
    sc_c[idx] = c;
    float hv = sigmoidf_(o_) * tanhf(c);
    sc_h[idx] = hv;
    __nv_bfloat16 h;
    __nv_bfloat16 l;
    bsplit(hv, &h, &l);
    sc_AH[b * KR + WQ + u] = h;
    sc_AL[b * KR + WQ + u] = l;
}

__global__ __launch_bounds__(256) void k_headsout(float* __restrict__ out, int s) {
    __shared__ float As[32][33];
    __shared__ float Bs[32][33];
    int tid = threadIdx.x;
    int n0 = blockIdx.x * 32;
    int m0 = blockIdx.y * 32;
    int rowL = tid >> 3;
    int k4 = (tid & 7) * 4;
    int tm = tid & 7;
    int tn = tid >> 3;
    float acc[4] = {};
    for (int k0 = 0; k0 < HQ; k0 += 32) {
        float4 a = *(const float4*)(sc_h + (long long)(m0 + rowL) * HQ + k0 + k4);
        float4 b = *(const float4*)(sc_HOW + (long long)(n0 + rowL) * HQ + k0 + k4);
        As[rowL][k4 + 0] = a.x; As[rowL][k4 + 1] = a.y; As[rowL][k4 + 2] = a.z; As[rowL][k4 + 3] = a.w;
        Bs[rowL][k4 + 0] = b.x; Bs[rowL][k4 + 1] = b.y; Bs[rowL][k4 + 2] = b.z; Bs[rowL][k4 + 3] = b.w;
        __syncthreads();
        #pragma unroll
        for (int k = 0; k < 32; k++) {
            float bv = Bs[tn][k];
            #pragma unroll
            for (int i = 0; i < 4; i++) acc[i] = fmaf(As[tm * 4 + i][k], bv, acc[i]);
        }
        __syncthreads();
    }
    int n = n0 + tn;
    float bb = sc_HOb[n];
    #pragma unroll
    for (int i = 0; i < 4; i++) {
        int m = m0 + tm * 4 + i;
        float v = acc[i] + bb;
        if (n < HRP) sc_heads[m * HRP + n] = v;
        else out[((long long)m * SQ + s) * OUTQ + (n - HRP)] = v;
    }
}

__global__ __launch_bounds__(128) void k_headproc() {
    __shared__ float sh[4];
    int b = blockIdx.x;
    int w = threadIdx.x;
    const float* hd = sc_heads + b * HRP;
    float rk = hd[w];
    float wk = hd[130 + w];
    float nr2 = blockSum128(rk * rk, sh);
    float nw2 = blockSum128(wk * wk, sh);
    __nv_bfloat16 h;
    __nv_bfloat16 l;
    bsplit(rk / fmaxf(sqrtf(nr2), 1e-12f), &h, &l);
    sc_keysH[b * WQ + w] = h;
    sc_keysL[b * WQ + w] = l;
    bsplit(wk / fmaxf(sqrtf(nw2), 1e-12f), &h, &l);
    sc_keysH[(128 + b) * WQ + w] = h;
    sc_keysL[(128 + b) * WQ + w] = l;
    if (w == 0) {
        sc_beta[b] = softplusf_(hd[128]);
        sc_gamma[b] = 1.0f + softplusf_(hd[129]);
        sc_beta[128 + b] = softplusf_(hd[258]);
        sc_gamma[128 + b] = 1.0f + softplusf_(hd[259]);
    }
    bsplit(sigmoidf_(hd[260 + w]), &h, &l);
    sc_erH[b * WQ + w] = h;
    sc_erL[b * WQ + w] = l;
    bsplit(tanhf(hd[388 + w]), &h, &l);
    sc_adH[b * WQ + w] = h;
    sc_adL[b * WQ + w] = l;
}

__global__ __launch_bounds__(512) void k_softmax512() {
    __shared__ float sh[16];
    __shared__ float bcv;
    int q = blockIdx.x;
    int tid = threadIdx.x;
    int lane = tid & 31;
    int wid = tid >> 5;
    float beta = sc_beta[q];
    float gamma = sc_gamma[q];
    const float* row = sc_sim + (long long)q * NQ;
    float v[32];
    float mx = -1e30f;
    #pragma unroll
    for (int i = 0; i < 32; i++) { v[i] = row[tid + i * 512]; mx = fmaxf(mx, v[i]); }
    #pragma unroll
    for (int o = 16; o; o >>= 1) mx = fmaxf(mx, __shfl_xor_sync(0xffffffffu, mx, o));
    if (lane == 0) sh[wid] = mx;
    __syncthreads();
    if (tid == 0) {
        float m = sh[0];
        #pragma unroll
        for (int i = 1; i < 16; i++) m = fmaxf(m, sh[i]);
        bcv = m;
    }
    __syncthreads();
    mx = bcv;
    float s = 0.f;
    #pragma unroll
    for (int i = 0; i < 32; i++) { v[i] = __expf(beta * (v[i] - mx)); s += v[i]; }
    __syncthreads();
    #pragma unroll
    for (int o = 16; o; o >>= 1) s += __shfl_xor_sync(0xffffffffu, s, o);
    if (lane == 0) sh[wid] = s;
    __syncthreads();
    if (tid == 0) {
        float t = 0.f;
        #pragma unroll
        for (int i = 0; i < 16; i++) t += sh[i];
        bcv = 1.0f / t;
    }
    __syncthreads();
    float inv = bcv;
    if (q < 128) {
        float* rw = sc_rw + (long long)q * NQ;
        __nv_bfloat16* rh = sc_rwH + (long long)q * NQ;
        __nv_bfloat16* rl = sc_rwL + (long long)q * NQ;
        #pragma unroll
        for (int i = 0; i < 32; i++) {
            int n = tid + i * 512;
            float nv = gamma * (v[i] * inv) + (1.0f - gamma) * rw[n];
            rw[n] = nv;
            __nv_bfloat16 h;
            __nv_bfloat16 l;
            bsplit(nv, &h, &l);
            rh[n] = h;
            rl[n] = l;
        }
    } else {
        __nv_bfloat16* wh = sc_wwH + (long long)(q - 128) * NQ;
        __nv_bfloat16* wl = sc_wwL + (long long)(q - 128) * NQ;
        float u = (1.0f - gamma) * (1.0f / (float)NQ);
        #pragma unroll
        for (int i = 0; i < 32; i++) {
            int n = tid + i * 512;
            float nv = gamma * (v[i] * inv) + u;
            __nv_bfloat16 h;
            __nv_bfloat16 l;
            bsplit(nv, &h, &l);
            wh[n] = h;
            wl[n] = l;
        }
    }
}

// ---------------- memupd + rv via bf16 MMA ----------------
#define MU_STR    136
#define MU_TILE   34816
#define MU_TOTAL  208896
#define MU_RWHOFF 67584
#define MU_RWLOFF 102400
#define MU_MEMHOFF 137216
#define MU_MEMLOFF 172032

__global__ __launch_bounds__(256) void k_memupd_rv() {
    extern __shared__ char dsm[];
    __shared__ float rowsq[128][2];
    __shared__ float sInv[128];
    int tid = threadIdx.x;
    int w = tid >> 5;
    int lane = tid & 31;
    int n0 = blockIdx.x * 128;

    // stage phase A: ww [b][n-tile], er/ad [b][w], all bf16 H/L
    for (int u = tid; u < 12288; u += 256) {
        int arr = u >> 11;
        int rem = u & 2047;
        int row = rem >> 4;
        int unit = rem & 15;
        unsigned dst = sptr(dsm + arr * MU_TILE + row * (MU_STR * 2) + unit * 16);
        const __nv_bfloat16* srcb;
        if (arr == 0)      srcb = sc_wwH + (long long)row * NQ + n0 + unit * 8;
        else if (arr == 1) srcb = sc_wwL + (long long)row * NQ + n0 + unit * 8;
        else if (arr == 2) srcb = sc_erH + row * WQ + unit * 8;
        else if (arr == 3) srcb = sc_erL + row * WQ + unit * 8;
        else if (arr == 4) srcb = sc_adH + row * WQ + unit * 8;
        else               srcb = sc_adL + row * WQ + unit * 8;
        cp16(dst, srcb);
    }
    cp_commit();
    cp_wait0();
    __syncthreads();

    __nv_bfloat16* WWH = (__nv_bfloat16*)(dsm);
    __nv_bfloat16* WWL = (__nv_bfloat16*)(dsm + MU_TILE);
    __nv_bfloat16* ERH = (__nv_bfloat16*)(dsm + 2 * MU_TILE);
    __nv_bfloat16* ERL = (__nv_bfloat16*)(dsm + 3 * MU_TILE);
    __nv_bfloat16* ADH = (__nv_bfloat16*)(dsm + 4 * MU_TILE);
    __nv_bfloat16* ADL = (__nv_bfloat16*)(dsm + 5 * MU_TILE);

    // phase A: E[n,w] = ww^T@er, A[n,w] = ww^T@ad  (k = b, trans loads on both)
    int mBase = (w >> 2) * 64;
    int nBase = (w & 3) * 32;
    float accE[4][4][4] = {};
    float accA[4][4][4] = {};
    for (int kk = 0; kk < 8; kk++) {
        unsigned ah[4][4];
        unsigned al[4][4];
        int g = lane >> 3;
        int arow = kk * 16 + (g >> 1) * 8 + (lane & 7);
        #pragma unroll
        for (int mt = 0; mt < 4; mt++) {
            int acol = mBase + mt * 16 + (g & 1) * 8;
            ldm_x4t(ah[mt], sptr(WWH + arow * MU_STR + acol));
            ldm_x4t(al[mt], sptr(WWL + arow * MU_STR + acol));
        }
        int brow = kk * 16 + (lane & 15);
        #pragma unroll
        for (int nt = 0; nt < 4; nt++) {
            int bcol = nBase + nt * 8;
            unsigned ebh[2];
            unsigned ebl[2];
            unsigned abh[2];
            unsigned abl[2];
            ldm_x2t(ebh, sptr(ERH + brow * MU_STR + bcol));
            ldm_x2t(ebl, sptr(ERL + brow * MU_STR + bcol));
            ldm_x2t(abh, sptr(ADH + brow * MU_STR + bcol));
            ldm_x2t(abl, sptr(ADL + brow * MU_STR + bcol));
            #pragma unroll
            for (int mt = 0; mt < 4; mt++) {
                mma_bf16(accE[mt][nt], ah[mt], ebh);
                mma_bf16(accE[mt][nt], ah[mt], ebl);
                mma_bf16(accE[mt][nt], al[mt], ebh);
                mma_bf16(accA[mt][nt], ah[mt], abh);
                mma_bf16(accA[mt][nt], ah[mt], abl);
                mma_bf16(accA[mt][nt], al[mt], abh);
            }
        }
    }
    __syncthreads();

    // stage rw for phase B (overlaps with update below)
    for (int u = tid; u < 4096; u += 256) {
        int arr = u >> 11;
        int rem = u & 2047;
        int row = rem >> 4;
        int unit = rem & 15;
        unsigned dst = sptr(dsm + (arr ? MU_RWLOFF : MU_RWHOFF) + row * (MU_STR * 2) + unit * 16);
        const __nv_bfloat16* srcb = (arr ? sc_rwL : sc_rwH) + (long long)row * NQ + n0 + unit * 8;
        cp16(dst, srcb);
    }
    cp_commit();

    // memory update (fp32) + stage new tile in smem
    float (*mns)[132] = (float(*)[132])dsm;
    #pragma unroll
    for (int mt = 0; mt < 4; mt++) {
        #pragma unroll
        for (int half = 0; half < 2; half++) {
            int r = mBase + mt * 16 + (lane >> 2) + half * 8;
            #pragma unroll
            for (int nt = 0; nt < 4; nt++) {
                int col = nBase + nt * 8 + (lane & 3) * 2;
                long long gi = (long long)(n0 + r) * WQ + col;
                float2 mv = *(float2*)&sc_mem[gi];
                float e0 = accE[mt][nt][half * 2 + 0];
                float e1 = accE[mt][nt][half * 2 + 1];
                float a0 = accA[mt][nt][half * 2 + 0];
                float a1 = accA[mt][nt][half * 2 + 1];
                float r0 = mv.x * (1.0f - e0) + a0;
                float r1 = mv.y * (1.0f - e1) + a1;
                *(float2*)&sc_mem[gi] = make_float2(r0, r1);
                mns[r][col] = r0;
                mns[r][col + 1] = r1;
            }
        }
    }
    __syncthreads();

    // row norms
    {
        int r = tid >> 1;
        int half = tid & 1;
        float s = 0.f;
        #pragma unroll
        for (int t = 0; t < 64; t += 4) {
            float4 vv = *(float4*)&mns[r][half * 64 + t];
            s += vv.x * vv.x + vv.y * vv.y + vv.z * vv.z + vv.w * vv.w;
        }
        rowsq[r][half] = s;
    }
    __syncthreads();
    if (tid < 128) {
        sInv[tid] = 1.0f / fmaxf(sqrtf(rowsq[tid][0] + rowsq[tid][1]), 1e-12f);
    }
    __syncthreads();

    // write normalized bf16 memory (gmem) + unnormalized bf16 split (smem, phase B)
    __nv_bfloat16* MEMH = (__nv_bfloat16*)(dsm + MU_MEMHOFF);
    __nv_bfloat16* MEML = (__nv_bfloat16*)(dsm + MU_MEMLOFF);
    for (int i = tid; i < 16384; i += 256) {
        int r = i >> 7;
        int c = i & 127;
        float v = mns[r][c];
        __nv_bfloat16 h;
        __nv_bfloat16 l;
        bsplit(v, &h, &l);
        MEMH[r * MU_STR + c] = h;
        MEML[r * MU_STR + c] = l;
        bsplit(v * sInv[r], &h, &l);
        long long o = (long long)(n0 + r) * WQ + c;
        sc_memnH[o] = h;
        sc_memnL[o] = l;
    }
    cp_wait0();
    __syncthreads();

    // phase B: rv partials = rw[:, tile] @ mem_new
    __nv_bfloat16* RWH = (__nv_bfloat16*)(dsm + MU_RWHOFF);
    __nv_bfloat16* RWL = (__nv_bfloat16*)(dsm + MU_RWLOFF);
    int mB2 = (w >> 1) * 32;
    int nB2 = (w & 1) * 64;
    float racc[2][8][4] = {};
    for (int kk = 0; kk < 8; kk++) {
        unsigned ah2[2][4];
        unsigned al2[2][4];
        #pragma unroll
        for (int mt = 0; mt < 2; mt++) {
            int ar = mB2 + mt * 16 + (lane & 15);
            int acol = kk * 16 + (lane >> 4) * 8;
            ldm_x4(ah2[mt], sptr(RWH + ar * MU_STR + acol));
            ldm_x4(al2[mt], sptr(RWL + ar * MU_STR + acol));
        }
        int brow = kk * 16 + (lane & 15);
        #pragma unroll
        for (int nt = 0; nt < 8; nt++) {
            int bcol = nB2 + nt * 8;
            unsigned bh[2];
            unsigned bl[2];
            ldm_x2t(bh, sptr(MEMH + brow * MU_STR + bcol));
            ldm_x2t(bl, sptr(MEML + brow * MU_STR + bcol));
            #pragma unroll
            for (int mt = 0; mt < 2; mt++) {
                mma_bf16(racc[mt][nt], ah2[mt], bh);
                mma_bf16(racc[mt][nt], ah2[mt], bl);
                mma_bf16(racc[mt][nt], al2[mt], bh);
            }
        }
    }
    float* dst = sc_rvpart + (long long)blockIdx.x * BQ * WQ;
    #pragma unroll
    for (int mt = 0; mt < 2; mt++) {
        int b = mB2 + mt * 16 + (lane >> 2);
        #pragma unroll
        for (int nt = 0; nt < 8; nt++) {
            int col = nB2 + nt * 8 + (lane & 3) * 2;
            *(float2*)&dst[b * WQ + col] = make_float2(racc[mt][nt][0], racc[mt][nt][1]);
            *(float2*)&dst[(b + 8) * WQ + col] = make_float2(racc[mt][nt][2], racc[mt][nt][3]);
        }
    }
}

__global__ __launch_bounds__(256) void k_rvreduce() {
    __shared__ float4 red[32][8];
    int tid = threadIdx.x;
    int outIdx = blockIdx.x * 32 + (tid >> 3);
    int sub = tid & 7;
    const float4* p = (const float4*)sc_rvpart;
    float4 s = make_float4(0.f, 0.f, 0.f, 0.f);
    #pragma unroll 4
    for (int i = 0; i < 16; i++) {
        float4 t = p[(long long)(sub + i * 8) * 4096 + outIdx];
        s.x += t.x; s.y += t.y; s.z += t.z; s.w += t.w;
    }
    red[tid >> 3][sub] = s;
    __syncthreads();
    if (sub == 0) {
        float4 a = make_float4(0.f, 0.f, 0.f, 0.f);
        #pragma unroll
        for (int i = 0; i < 8; i++) {
            float4 t = red[tid >> 3][i];
            a.x += t.x; a.y += t.y; a.z += t.z; a.w += t.w;
        }
        int b = outIdx >> 5;
        int c0 = (outIdx & 31) * 4;
        __nv_bfloat16 h0, l0, h1, l1, h2, l2, h3, l3;
        bsplit(a.x, &h0, &l0);
        bsplit(a.y, &h1, &l1);
        bsplit(a.z, &h2, &l2);
        bsplit(a.w, &h3, &l3);
        int o = b * KR + c0;
        st_bf2(&sc_AH[o], h0, h1);
        st_bf2(&sc_AH[o + 2], h2, h3);
        st_bf2(&sc_AL[o], l0, l1);
        st_bf2(&sc_AL[o + 2], l2, l3);
    }
}

// ---------------- host launcher ----------------
extern "C" void kernel_launch(void* const* d_in, const int* in_sizes, int n_in,
                              void* d_out, int out_size) {
    const float* x = (const float*)d_in[0];
    const float* memory = (const float*)d_in[1];
    const float* Wih = (const float*)d_in[2];
    const float* Whh = (const float*)d_in[3];
    const float* bih = (const float*)d_in[4];
    const float* bhh = (const float*)d_in[5];
    const float* Wout = (const float*)d_in[6];
    const float* bout = (const float*)d_in[7];
    const float* rkW = (const float*)d_in[8];
    const float* rkb = (const float*)d_in[9];
    const float* rbW = (const float*)d_in[10];
    const float* rbb = (const float*)d_in[11];
    const float* rgW = (const float*)d_in[12];
    const float* rgb = (const float*)d_in[13];
    const float* wkW = (const float*)d_in[14];
    const float* wkb = (const float*)d_in[15];
    const float* wbW = (const float*)d_in[16];
    const float* wbb = (const float*)d_in[17];
    const float* wgW = (const float*)d_in[18];
    const float* wgb = (const float*)d_in[19];
    const float* erW = (const float*)d_in[20];
    const float* erb = (const float*)d_in[21];
    const float* adW = (const float*)d_in[22];
    const float* adb = (const float*)d_in[23];
    const float* pW = (const float*)d_in[24];
    const float* pb = (const float*)d_in[25];
    float* out = (float*)d_out;

    cudaFuncSetAttribute(k_lstm_mma, cudaFuncAttributeMaxDynamicSharedMemorySize, 2 * L_BUFB);
    cudaFuncSetAttribute(k_sim_mma, cudaFuncAttributeMaxDynamicSharedMemorySize, 139264);
    cudaFuncSetAttribute(k_memupd_rv, cudaFuncAttributeMaxDynamicSharedMemorySize, MU_TOTAL);

    long long setup_total = (long long)G4 * K1 + G4 + (long long)CP * HQ + (long long)HRP * CP;
    k_setup_w<<<(int)((setup_total + 255) / 256), 256>>>(Wih, Whh, bih, bhh, Wout,
                                                         rkW, rbW, rgW, wkW, wbW, wgW, erW, adW);
    k_setup_x<<<(int)(((long long)SQ * BQ * INQ + 255) / 256), 256>>>(x);
    k_initmem<<<2048 + 17984, 256>>>(memory);
    k_biases<<<HOW, 128>>>(bout, pW, pb, rkW, rbW, rgW, wkW, wbW, wgW, erW, adW,
                           rkb, rbb, rgb, wkb, wbb, wgb, erb, adb);
    k_fold<<<dim3(HQ / 32, 34), 256>>>(pW, Wout);

    for (int s = 0; s < SQ; s++) {
        k_lstm_mma<<<dim3(G4 / 128, 1, NZ), 256, 2 * L_BUFB>>>(s);
        k_gates<<<(BQ * HQ + 255) / 256, 256>>>();
        k_headsout<<<dim3(HOW / 32, BQ / 32), 256>>>(out, s);
        k_headproc<<<BQ, 128>>>();
        k_sim_mma<<<dim3(NQ / 128, 2), 256, 139264>>>();
        k_softmax512<<<2 * BQ, 512>>>();
        k_memupd_rv<<<NQ / 128, 256, MU_TOTAL>>>();
        k_rvreduce<<<128, 256>>>();
    }
}